// round 9
// baseline (speedup 1.0000x reference)
#include <cuda_runtime.h>
#include <cuda_bf16.h>
#include <cstdint>

// Problem constants (fixed dataset)
#define NMAX 50000
#define RREL 8
#define FIN  128
#define NB   (NMAX * RREL)          // 400000 segment bins
#define EMAX 800000

// ---------------- device scratch (allocation-free) ----------------
__device__ float g_h0[NMAX * FIN];
__device__ float g_h1[NMAX * FIN];
__device__ int   g_cnt[NB];
__device__ int   g_off[NB + 64];
__device__ int   g_cur[NB];
__device__ int   g_srcs[EMAX + 64];
__device__ float g_inv[NB];
__device__ int   g_bsum[256];
// Pre-split, pre-swizzled B chunk images (hi/lo) per layer
__device__ unsigned char g_B0hi[294912];
__device__ unsigned char g_B0lo[294912];
__device__ unsigned char g_B1hi[294912];
__device__ unsigned char g_B1lo[294912];
__device__ unsigned char g_B2hi[36864];
__device__ unsigned char g_B2lo[36864];

// ---------------- PTX helpers (baseline sm_80-level, no 'a' features) ----------
__device__ __forceinline__ uint32_t smem_u32(const void* p) {
    uint32_t a;
    asm("{ .reg .u64 t; cvta.to.shared.u64 t, %1; cvt.u32.u64 %0, t; }" : "=r"(a) : "l"(p));
    return a;
}
__device__ __forceinline__ void ldsm4(uint32_t* r, uint32_t addr) {
    asm volatile("ldmatrix.sync.aligned.m8n8.x4.shared.b16 {%0,%1,%2,%3}, [%4];"
                 : "=r"(r[0]), "=r"(r[1]), "=r"(r[2]), "=r"(r[3]) : "r"(addr));
}
__device__ __forceinline__ void ldsm2(uint32_t* r, uint32_t addr) {
    asm volatile("ldmatrix.sync.aligned.m8n8.x2.shared.b16 {%0,%1}, [%2];"
                 : "=r"(r[0]), "=r"(r[1]) : "r"(addr));
}
__device__ __forceinline__ void mma16816(float* c, const uint32_t* a, const uint32_t* b) {
    asm volatile("mma.sync.aligned.m16n8k16.row.col.f32.bf16.bf16.f32 "
                 "{%0,%1,%2,%3}, {%4,%5,%6,%7}, {%8,%9}, {%0,%1,%2,%3};"
                 : "+f"(c[0]), "+f"(c[1]), "+f"(c[2]), "+f"(c[3])
                 : "r"(a[0]), "r"(a[1]), "r"(a[2]), "r"(a[3]), "r"(b[0]), "r"(b[1]));
}
__device__ __forceinline__ void cpa16(uint32_t smem, const void* g) {
    asm volatile("cp.async.cg.shared.global [%0], [%1], 16;" :: "r"(smem), "l"(g));
}
#define CP_COMMIT() asm volatile("cp.async.commit_group;" ::: "memory")
#define CP_WAIT0()  asm volatile("cp.async.wait_group 0;" ::: "memory")
#define CP_WAIT1()  asm volatile("cp.async.wait_group 1;" ::: "memory")

// hi/lo bf16 split + pack pair into one u32 (low half = first element)
__device__ __forceinline__ void split_pack(float a, float b, uint32_t& hi, uint32_t& lo) {
    __nv_bfloat16 ah = __float2bfloat16(a), bh = __float2bfloat16(b);
    __nv_bfloat162 hh; hh.x = ah; hh.y = bh;
    hi = *reinterpret_cast<uint32_t*>(&hh);
    __nv_bfloat162 ll;
    ll.x = __float2bfloat16(a - __bfloat162float(ah));
    ll.y = __float2bfloat16(b - __bfloat162float(bh));
    lo = *reinterpret_cast<uint32_t*>(&ll);
}

// ---------------- CSR build ----------------
__global__ void zero_cnt_k() {
    int i = blockIdx.x * blockDim.x + threadIdx.x;
    if (i < NB) g_cnt[i] = 0;
}
__global__ void count_k(const int* __restrict__ dst, const int* __restrict__ et, int e) {
    int i = blockIdx.x * blockDim.x + threadIdx.x;
    if (i < e) atomicAdd(&g_cnt[dst[i] * RREL + et[i]], 1);
}

#define SCAN_T 256
#define SCAN_I 8
#define SCAN_E (SCAN_T * SCAN_I)                 // 2048
#define SCAN_NBLK ((NB + SCAN_E - 1) / SCAN_E)   // 196

__global__ void scan1_k() {
    __shared__ int sh[SCAN_T];
    int b = blockIdx.x, t = threadIdx.x;
    int base = b * SCAN_E + t * SCAN_I;
    int v[SCAN_I]; int s = 0;
#pragma unroll
    for (int i = 0; i < SCAN_I; i++) {
        int idx = base + i;
        v[i] = (idx < NB) ? g_cnt[idx] : 0;
        s += v[i];
    }
    sh[t] = s; __syncthreads();
    for (int off = 1; off < SCAN_T; off <<= 1) {
        int x = (t >= off) ? sh[t - off] : 0;
        __syncthreads();
        sh[t] += x;
        __syncthreads();
    }
    if (t == SCAN_T - 1) g_bsum[b] = sh[t];
    int excl = sh[t] - s;
#pragma unroll
    for (int i = 0; i < SCAN_I; i++) {
        int idx = base + i;
        if (idx < NB) g_off[idx] = excl;
        excl += v[i];
    }
}
__global__ void scan2_k() {
    __shared__ int sh[SCAN_T];
    int t = threadIdx.x;
    int v = (t < SCAN_NBLK) ? g_bsum[t] : 0;
    sh[t] = v; __syncthreads();
    for (int off = 1; off < SCAN_T; off <<= 1) {
        int x = (t >= off) ? sh[t - off] : 0;
        __syncthreads();
        sh[t] += x;
        __syncthreads();
    }
    if (t < SCAN_NBLK) g_bsum[t] = sh[t] - v;
}
__global__ void scan3_k(int e) {
    int i = blockIdx.x * blockDim.x + threadIdx.x;
    if (i < NB) {
        int o = g_off[i] + g_bsum[i / SCAN_E];
        g_off[i] = o;
        g_cur[i] = o;
        int c = g_cnt[i];
        g_inv[i] = 1.0f / (float)(c > 1 ? c : 1);
    }
    if (i == 0) g_off[NB] = e;
}
__global__ void fill_k(const int* __restrict__ src, const int* __restrict__ dst,
                       const int* __restrict__ et, int e) {
    int i = blockIdx.x * blockDim.x + threadIdx.x;
    if (i < e) {
        int bin = dst[i] * RREL + et[i];
        int slot = atomicAdd(&g_cur[bin], 1);
        g_srcs[slot] = src[i];
    }
}

// ---------------- B precompute: split + swizzle weight chunk images ------------
// Image: 9 chunks x [NTB rows x 256B], chunk-XOR swizzle by (row & 7).
// chunk 0 = root (128 x FOUT), chunk t>0 = W[t-1] (128 x FOUT); B row ln = out col.
template<int FOUT>
__global__ void conv_b_k(const float* __restrict__ root, const float* __restrict__ W,
                         unsigned char* __restrict__ Dhi, unsigned char* __restrict__ Dlo) {
    constexpr int NTB = (FOUT == 128) ? 128 : 16;
    int i = blockIdx.x * blockDim.x + threadIdx.x;
    if (i >= 9 * 16 * NTB) return;
    int t = i / (16 * NTB);
    int j = i % (16 * NTB);
    int cc = j / NTB, ln = j % NTB;
    float v[8];
#pragma unroll
    for (int kk = 0; kk < 8; kk++) {
        int k = cc * 8 + kk;
        v[kk] = (t == 0) ? root[k * FOUT + ln]
                         : W[((size_t)(t - 1) * 128 + k) * FOUT + ln];
    }
    uint32_t hi[4], lo[4];
#pragma unroll
    for (int q = 0; q < 4; q++) split_pack(v[2*q], v[2*q+1], hi[q], lo[q]);
    uint32_t off = (uint32_t)t * (NTB * 256) + (uint32_t)ln * 256 + ((uint32_t)(cc ^ (ln & 7)) << 4);
    *reinterpret_cast<uint4*>(Dhi + off) = make_uint4(hi[0], hi[1], hi[2], hi[3]);
    *reinterpret_cast<uint4*>(Dlo + off) = make_uint4(lo[0], lo[1], lo[2], lo[3]);
}

// ---------------- fully-fused RGCN layer ---------------------------------------
// out[node] = (relu)( X[node]@root + bias + sum_r mean_{src in N_r}(X[src]) @ W_r )
// Per block: 128 nodes. 9 K-chunks: chunk 0 = self rows, chunk r = mean-aggregated
// rows of relation r-1, built in smem from gathers of X (L2-resident).
// 512 threads = 16 warps. FOUT=128: warp grid 4(m) x 4(n); FOUT=16: 8(m) x 2(n).
template<int FOUT>
__global__ void __launch_bounds__(512, (FOUT == 128) ? 1 : 2)
rgcn_fused_k(const float* __restrict__ X,
             const unsigned char* __restrict__ Bhi,
             const unsigned char* __restrict__ Blo,
             const float* __restrict__ bias,
             float* __restrict__ out, int n, int relu) {
    constexpr int NTB = (FOUT == 128) ? 128 : 16;
    constexpr int WNV = (FOUT == 128) ? 32 : 8;
    constexpr int NB8 = WNV / 8;                 // 4 or 1
    constexpr int MT  = (FOUT == 128) ? 2 : 1;
    constexpr int TB  = NTB * 256;               // chunk image bytes (hi or lo)
    constexpr int A_HI = 0, A_LO = 32768, B_BASE = 65536, BSTEP = 2 * TB;

    extern __shared__ char sm[];
    const uint32_t sb = smem_u32(sm);
    const int tid = threadIdx.x, lane = tid & 31, wid = tid >> 5;
    const int wm = (FOUT == 128) ? (wid & 3) : (wid >> 1);
    const int wn = (FOUT == 128) ? (wid >> 2) : (wid & 1);
    const int m0 = blockIdx.x * 128;
    const int lane4 = lane * 4;

    // prologue: B(0) into buf 0
    for (int i = tid; i < NTB * 16; i += 512) {
        cpa16(sb + B_BASE + i * 16, Bhi + i * 16);
        cpa16(sb + B_BASE + TB + i * 16, Blo + i * 16);
    }
    CP_COMMIT();

    // fragment addressing (lane-invariant)
    const int sub  = lane >> 3;
    const int rowa_base = (FOUT == 128) ? wm * 32 : wm * 16;
    const int rowa = rowa_base + (sub & 1) * 8 + (lane & 7);
    const int csel = sub >> 1;
    const int rs   = lane & 7;
    const int lb   = lane & 15;
    const int subb = lb >> 3;
    const int rsb  = lb & 7;

    float acc[MT][NB8][4];
#pragma unroll
    for (int mt = 0; mt < MT; mt++)
#pragma unroll
        for (int nb = 0; nb < NB8; nb++)
#pragma unroll
            for (int q = 0; q < 4; q++) acc[mt][nb][q] = 0.f;

    int buf = 0;
    for (int c = 0; c < 9; c++) {
        // prefetch next chunk's B (overlaps gather + MMA)
        if (c + 1 < 9) {
            uint32_t bdst = sb + B_BASE + (buf ^ 1) * BSTEP;
            const unsigned char* shi = Bhi + (size_t)(c + 1) * TB;
            const unsigned char* slo = Blo + (size_t)(c + 1) * TB;
            for (int i = tid; i < NTB * 16; i += 512) {
                cpa16(bdst + i * 16, shi + i * 16);
                cpa16(bdst + TB + i * 16, slo + i * 16);
            }
            CP_COMMIT();
        }

        // ---- gather phase: build A chunk (128 x 128) in smem, 8 nodes per warp ----
#pragma unroll 2
        for (int j = 0; j < 8; j++) {
            int row = wid * 8 + j;
            int node = m0 + row;
            float4 v = make_float4(0.f, 0.f, 0.f, 0.f);
            if (node < n) {
                if (c == 0) {
                    v = *reinterpret_cast<const float4*>(X + (size_t)node * 128 + lane4);
                } else {
                    int b = node * RREL + (c - 1);
                    int s = g_off[b];
                    const int s1 = g_off[b + 1];
                    if (s < s1) {
                        float4 a0 = make_float4(0.f, 0.f, 0.f, 0.f);
                        float4 a1 = make_float4(0.f, 0.f, 0.f, 0.f);
                        for (; s + 2 <= s1; s += 2) {
                            int j0 = g_srcs[s], j1 = g_srcs[s + 1];
                            const float4 t0 = *reinterpret_cast<const float4*>(X + (size_t)j0 * 128 + lane4);
                            const float4 t1 = *reinterpret_cast<const float4*>(X + (size_t)j1 * 128 + lane4);
                            a0.x += t0.x; a0.y += t0.y; a0.z += t0.z; a0.w += t0.w;
                            a1.x += t1.x; a1.y += t1.y; a1.z += t1.z; a1.w += t1.w;
                        }
                        if (s < s1) {
                            const float4 t0 = *reinterpret_cast<const float4*>(X + (size_t)g_srcs[s] * 128 + lane4);
                            a0.x += t0.x; a0.y += t0.y; a0.z += t0.z; a0.w += t0.w;
                        }
                        float inv = g_inv[b];
                        v.x = (a0.x + a1.x) * inv;
                        v.y = (a0.y + a1.y) * inv;
                        v.z = (a0.z + a1.z) * inv;
                        v.w = (a0.w + a1.w) * inv;
                    }
                }
            }
            uint32_t h0, l0, h1, l1;
            split_pack(v.x, v.y, h0, l0);
            split_pack(v.z, v.w, h1, l1);
            uint32_t off = (uint32_t)row * 256 + ((uint32_t)((lane >> 1) ^ (row & 7)) << 4)
                         + (uint32_t)(lane & 1) * 8;
            *reinterpret_cast<uint2*>(sm + A_HI + off) = make_uint2(h0, h1);
            *reinterpret_cast<uint2*>(sm + A_LO + off) = make_uint2(l0, l1);
        }

        if (c + 1 < 9) { CP_WAIT1(); } else { CP_WAIT0(); }
        __syncthreads();   // A chunk + B chunk resident

        // ---- MMA phase: 3-product hi/lo accumulate into persistent regs ----
        const uint32_t bh_base = sb + B_BASE + buf * BSTEP;
        const uint32_t bl_base = bh_base + TB;
#pragma unroll
        for (int ks = 0; ks < 8; ks++) {
            uint32_t ca = (uint32_t)((2 * ks + csel) ^ rs) << 4;
            uint32_t ah0[4], al0[4], ah1[4], al1[4];
            ldsm4(ah0, sb + A_HI + (uint32_t)rowa * 256 + ca);
            ldsm4(al0, sb + A_LO + (uint32_t)rowa * 256 + ca);
            if (MT == 2) {
                ldsm4(ah1, sb + A_HI + (uint32_t)(rowa + 16) * 256 + ca);
                ldsm4(al1, sb + A_LO + (uint32_t)(rowa + 16) * 256 + ca);
            }
            uint32_t cb = (uint32_t)((2 * ks + subb) ^ rsb) << 4;
#pragma unroll
            for (int nb = 0; nb < NB8; nb++) {
                uint32_t rowb = (uint32_t)(wn * WNV + nb * 8 + rsb);
                uint32_t bh[2], bl[2];
                ldsm2(bh, bh_base + rowb * 256 + cb);
                ldsm2(bl, bl_base + rowb * 256 + cb);
                mma16816(acc[0][nb], ah0, bh);
                mma16816(acc[0][nb], ah0, bl);
                mma16816(acc[0][nb], al0, bh);
                if (MT == 2) {
                    mma16816(acc[1][nb], ah1, bh);
                    mma16816(acc[1][nb], ah1, bl);
                    mma16816(acc[1][nb], al1, bh);
                }
            }
        }
        __syncthreads();   // MMA done before next gather overwrites A
        buf ^= 1;
    }

    // ---- epilogue: bias (+relu), write output ----
#pragma unroll
    for (int mt = 0; mt < MT; mt++) {
        int row = m0 + rowa_base + mt * 16 + (lane >> 2);
#pragma unroll
        for (int nb = 0; nb < NB8; nb++) {
            int col = wn * WNV + nb * 8 + (lane & 3) * 2;
            float b0 = bias[col], b1 = bias[col + 1];
            float v0 = acc[mt][nb][0] + b0;
            float v1 = acc[mt][nb][1] + b1;
            float v2 = acc[mt][nb][2] + b0;
            float v3 = acc[mt][nb][3] + b1;
            if (relu) {
                v0 = fmaxf(v0, 0.f); v1 = fmaxf(v1, 0.f);
                v2 = fmaxf(v2, 0.f); v3 = fmaxf(v3, 0.f);
            }
            if (row < n)
                *reinterpret_cast<float2*>(out + (size_t)row * FOUT + col) = make_float2(v0, v1);
            if (row + 8 < n)
                *reinterpret_cast<float2*>(out + (size_t)(row + 8) * FOUT + col) = make_float2(v2, v3);
        }
    }
}

// ---------------- host ----------------
extern "C" void kernel_launch(void* const* d_in, const int* in_sizes, int n_in,
                              void* d_out, int out_size) {
    const float* x  = (const float*)d_in[0];
    const int* eidx = (const int*)d_in[1];
    const int* et   = (const int*)d_in[2];
    const float* w0 = (const float*)d_in[3];
    const float* r0 = (const float*)d_in[4];
    const float* b0 = (const float*)d_in[5];
    const float* w1 = (const float*)d_in[6];
    const float* r1 = (const float*)d_in[7];
    const float* b1 = (const float*)d_in[8];
    const float* w2 = (const float*)d_in[9];
    const float* r2 = (const float*)d_in[10];
    const float* b2 = (const float*)d_in[11];
    float* out = (float*)d_out;

    int n = in_sizes[0] / FIN;   // 50000
    int e = in_sizes[2];         // 800000
    const int* src = eidx;
    const int* dst = eidx + e;

    float *h0, *h1;
    unsigned char *B0hi, *B0lo, *B1hi, *B1lo, *B2hi, *B2lo;
    cudaGetSymbolAddress((void**)&h0, g_h0);
    cudaGetSymbolAddress((void**)&h1, g_h1);
    cudaGetSymbolAddress((void**)&B0hi, g_B0hi);
    cudaGetSymbolAddress((void**)&B0lo, g_B0lo);
    cudaGetSymbolAddress((void**)&B1hi, g_B1hi);
    cudaGetSymbolAddress((void**)&B1lo, g_B1lo);
    cudaGetSymbolAddress((void**)&B2hi, g_B2hi);
    cudaGetSymbolAddress((void**)&B2lo, g_B2lo);

    const int SMEM128 = 65536 + 2 * (2 * 128 * 256);   // 196608
    const int SMEM16  = 65536 + 2 * (2 * 16 * 256);    // 81920
    cudaFuncSetAttribute(rgcn_fused_k<128>, cudaFuncAttributeMaxDynamicSharedMemorySize, SMEM128);
    cudaFuncSetAttribute(rgcn_fused_k<16>,  cudaFuncAttributeMaxDynamicSharedMemorySize, SMEM16);

    // Weight image precompute (independent of graph build)
    conv_b_k<128><<<(9 * 16 * 128 + 255) / 256, 256>>>(r0, w0, B0hi, B0lo);
    conv_b_k<128><<<(9 * 16 * 128 + 255) / 256, 256>>>(r1, w1, B1hi, B1lo);
    conv_b_k<16><<<(9 * 16 * 16 + 255) / 256, 256>>>(r2, w2, B2hi, B2lo);

    // CSR build (edge structure shared by all 3 layers)
    zero_cnt_k<<<(NB + 255) / 256, 256>>>();
    count_k<<<(e + 255) / 256, 256>>>(dst, et, e);
    scan1_k<<<SCAN_NBLK, SCAN_T>>>();
    scan2_k<<<1, SCAN_T>>>();
    scan3_k<<<(NB + 255) / 256, 256>>>(e);
    fill_k<<<(e + 255) / 256, 256>>>(src, dst, et, e);

    int mblocks = (n + 127) / 128;   // 391
    // Fully-fused layers: gather(+mean) -> GEMM -> bias/relu, no Y materialization
    rgcn_fused_k<128><<<mblocks, 512, SMEM128>>>(x,  B0hi, B0lo, b0, h0, n, 1);
    rgcn_fused_k<128><<<mblocks, 512, SMEM128>>>(h0, B1hi, B1lo, b1, h1, n, 1);
    rgcn_fused_k<16><<<mblocks, 512, SMEM16>>>(h1, B2hi, B2lo, b2, out, n, 0);
}

// round 10
// speedup vs baseline: 1.1643x; 1.1643x over previous
#include <cuda_runtime.h>
#include <cuda_bf16.h>
#include <cstdint>

// Problem constants (fixed dataset)
#define NMAX 50000
#define RREL 8
#define FIN  128
#define NB   (NMAX * RREL)          // 400000 segment bins
#define EMAX 800000

// ---------------- device scratch (allocation-free) ----------------
__device__ float g_h0[NMAX * FIN];
__device__ float g_h1[NMAX * FIN];
__device__ int   g_cnt[NB];
__device__ int   g_off[NB + 64];
__device__ int   g_cur[NB];
__device__ int   g_srcs[EMAX + 64];
__device__ float g_inv[NB];
__device__ int   g_bsum[256];
// Pre-split, pre-swizzled B chunk images (hi/lo) per layer
__device__ unsigned char g_B0hi[294912];
__device__ unsigned char g_B0lo[294912];
__device__ unsigned char g_B1hi[294912];
__device__ unsigned char g_B1lo[294912];
__device__ unsigned char g_B2hi[36864];
__device__ unsigned char g_B2lo[36864];

// ---------------- PTX helpers (baseline sm_80-level, no 'a' features) ----------
__device__ __forceinline__ uint32_t smem_u32(const void* p) {
    uint32_t a;
    asm("{ .reg .u64 t; cvta.to.shared.u64 t, %1; cvt.u32.u64 %0, t; }" : "=r"(a) : "l"(p));
    return a;
}
__device__ __forceinline__ void ldsm4(uint32_t* r, uint32_t addr) {
    asm volatile("ldmatrix.sync.aligned.m8n8.x4.shared.b16 {%0,%1,%2,%3}, [%4];"
                 : "=r"(r[0]), "=r"(r[1]), "=r"(r[2]), "=r"(r[3]) : "r"(addr));
}
__device__ __forceinline__ void ldsm2(uint32_t* r, uint32_t addr) {
    asm volatile("ldmatrix.sync.aligned.m8n8.x2.shared.b16 {%0,%1}, [%2];"
                 : "=r"(r[0]), "=r"(r[1]) : "r"(addr));
}
__device__ __forceinline__ void mma16816(float* c, const uint32_t* a, const uint32_t* b) {
    asm volatile("mma.sync.aligned.m16n8k16.row.col.f32.bf16.bf16.f32 "
                 "{%0,%1,%2,%3}, {%4,%5,%6,%7}, {%8,%9}, {%0,%1,%2,%3};"
                 : "+f"(c[0]), "+f"(c[1]), "+f"(c[2]), "+f"(c[3])
                 : "r"(a[0]), "r"(a[1]), "r"(a[2]), "r"(a[3]), "r"(b[0]), "r"(b[1]));
}
__device__ __forceinline__ void cpa16(uint32_t smem, const void* g) {
    asm volatile("cp.async.cg.shared.global [%0], [%1], 16;" :: "r"(smem), "l"(g));
}
#define CP_COMMIT() asm volatile("cp.async.commit_group;" ::: "memory")
#define CP_WAIT0()  asm volatile("cp.async.wait_group 0;" ::: "memory")
#define CP_WAIT1()  asm volatile("cp.async.wait_group 1;" ::: "memory")

// hi/lo bf16 split + pack pair into one u32 (low half = first element)
__device__ __forceinline__ void split_pack(float a, float b, uint32_t& hi, uint32_t& lo) {
    __nv_bfloat16 ah = __float2bfloat16(a), bh = __float2bfloat16(b);
    __nv_bfloat162 hh; hh.x = ah; hh.y = bh;
    hi = *reinterpret_cast<uint32_t*>(&hh);
    __nv_bfloat162 ll;
    ll.x = __float2bfloat16(a - __bfloat162float(ah));
    ll.y = __float2bfloat16(b - __bfloat162float(bh));
    lo = *reinterpret_cast<uint32_t*>(&ll);
}

// ---------------- CSR build ----------------
__global__ void zero_cnt_k() {
    int i = blockIdx.x * blockDim.x + threadIdx.x;
    if (i < NB) g_cnt[i] = 0;
}
__global__ void count_k(const int* __restrict__ dst, const int* __restrict__ et, int e) {
    int i = blockIdx.x * blockDim.x + threadIdx.x;
    if (i < e) atomicAdd(&g_cnt[dst[i] * RREL + et[i]], 1);
}

#define SCAN_T 256
#define SCAN_I 8
#define SCAN_E (SCAN_T * SCAN_I)                 // 2048
#define SCAN_NBLK ((NB + SCAN_E - 1) / SCAN_E)   // 196

__global__ void scan1_k() {
    __shared__ int sh[SCAN_T];
    int b = blockIdx.x, t = threadIdx.x;
    int base = b * SCAN_E + t * SCAN_I;
    int v[SCAN_I]; int s = 0;
#pragma unroll
    for (int i = 0; i < SCAN_I; i++) {
        int idx = base + i;
        v[i] = (idx < NB) ? g_cnt[idx] : 0;
        s += v[i];
    }
    sh[t] = s; __syncthreads();
    for (int off = 1; off < SCAN_T; off <<= 1) {
        int x = (t >= off) ? sh[t - off] : 0;
        __syncthreads();
        sh[t] += x;
        __syncthreads();
    }
    if (t == SCAN_T - 1) g_bsum[b] = sh[t];
    int excl = sh[t] - s;
#pragma unroll
    for (int i = 0; i < SCAN_I; i++) {
        int idx = base + i;
        if (idx < NB) g_off[idx] = excl;
        excl += v[i];
    }
}
__global__ void scan2_k() {
    __shared__ int sh[SCAN_T];
    int t = threadIdx.x;
    int v = (t < SCAN_NBLK) ? g_bsum[t] : 0;
    sh[t] = v; __syncthreads();
    for (int off = 1; off < SCAN_T; off <<= 1) {
        int x = (t >= off) ? sh[t - off] : 0;
        __syncthreads();
        sh[t] += x;
        __syncthreads();
    }
    if (t < SCAN_NBLK) g_bsum[t] = sh[t] - v;
}
__global__ void scan3_k(int e) {
    int i = blockIdx.x * blockDim.x + threadIdx.x;
    if (i < NB) {
        int o = g_off[i] + g_bsum[i / SCAN_E];
        g_off[i] = o;
        g_cur[i] = o;
        int c = g_cnt[i];
        g_inv[i] = 1.0f / (float)(c > 1 ? c : 1);
    }
    if (i == 0) g_off[NB] = e;
}
__global__ void fill_k(const int* __restrict__ src, const int* __restrict__ dst,
                       const int* __restrict__ et, int e) {
    int i = blockIdx.x * blockDim.x + threadIdx.x;
    if (i < e) {
        int bin = dst[i] * RREL + et[i];
        int slot = atomicAdd(&g_cur[bin], 1);
        g_srcs[slot] = src[i];
    }
}

// ---------------- B precompute: split + swizzle weight chunk images ------------
template<int FOUT>
__global__ void conv_b_k(const float* __restrict__ root, const float* __restrict__ W,
                         unsigned char* __restrict__ Dhi, unsigned char* __restrict__ Dlo) {
    constexpr int NTB = (FOUT == 128) ? 128 : 16;
    int i = blockIdx.x * blockDim.x + threadIdx.x;
    if (i >= 9 * 16 * NTB) return;
    int t = i / (16 * NTB);
    int j = i % (16 * NTB);
    int cc = j / NTB, ln = j % NTB;
    float v[8];
#pragma unroll
    for (int kk = 0; kk < 8; kk++) {
        int k = cc * 8 + kk;
        v[kk] = (t == 0) ? root[k * FOUT + ln]
                         : W[((size_t)(t - 1) * 128 + k) * FOUT + ln];
    }
    uint32_t hi[4], lo[4];
#pragma unroll
    for (int q = 0; q < 4; q++) split_pack(v[2*q], v[2*q+1], hi[q], lo[q]);
    uint32_t off = (uint32_t)t * (NTB * 256) + (uint32_t)ln * 256 + ((uint32_t)(cc ^ (ln & 7)) << 4);
    *reinterpret_cast<uint4*>(Dhi + off) = make_uint4(hi[0], hi[1], hi[2], hi[3]);
    *reinterpret_cast<uint4*>(Dlo + off) = make_uint4(lo[0], lo[1], lo[2], lo[3]);
}

// ---------------- fully-fused RGCN layer (MLP-optimized gather) ----------------
// out[node] = (relu)( X[node]@root + bias + sum_r mean_{src in N_r}(X[src]) @ W_r )
// Per block: 128 nodes, 512 threads = 16 warps. CSR offsets/inv staged in smem;
// gather iterates 4 rows in lockstep for MLP ~8.
template<int FOUT>
__global__ void __launch_bounds__(512, (FOUT == 128) ? 1 : 2)
rgcn_fused_k(const float* __restrict__ X,
             const unsigned char* __restrict__ Bhi,
             const unsigned char* __restrict__ Blo,
             const float* __restrict__ bias,
             float* __restrict__ out, int n, int relu) {
    constexpr int NTB = (FOUT == 128) ? 128 : 16;
    constexpr int WNV = (FOUT == 128) ? 32 : 8;
    constexpr int NB8 = WNV / 8;                 // 4 or 1
    constexpr int MT  = (FOUT == 128) ? 2 : 1;
    constexpr int TB  = NTB * 256;               // chunk image bytes (hi or lo)
    constexpr int A_HI = 0, A_LO = 32768, B_BASE = 65536, BSTEP = 2 * TB;
    constexpr int S_OFF = B_BASE + 2 * BSTEP;    // 1025 ints
    constexpr int S_INV = S_OFF + 4352;          // 1024 floats

    extern __shared__ char sm[];
    const uint32_t sb = smem_u32(sm);
    const int tid = threadIdx.x, lane = tid & 31, wid = tid >> 5;
    const int wm = (FOUT == 128) ? (wid & 3) : (wid >> 1);
    const int wn = (FOUT == 128) ? (wid >> 2) : (wid & 1);
    const int m0 = blockIdx.x * 128;
    const int lane4 = lane * 4;

    // prologue: B(0) into buf 0
    for (int i = tid; i < NTB * 16; i += 512) {
        cpa16(sb + B_BASE + i * 16, Bhi + i * 16);
        cpa16(sb + B_BASE + TB + i * 16, Blo + i * 16);
    }
    CP_COMMIT();

    // stage CSR offsets (+ sentinel) and inverse-degree weights into smem
    for (int i = tid; i < 1025; i += 512) {
        int idx = m0 * RREL + i;
        if (idx > NB) idx = NB;
        *reinterpret_cast<int*>(sm + S_OFF + i * 4) = g_off[idx];
    }
    for (int i = tid; i < 1024; i += 512) {
        int idx = m0 * RREL + i;
        if (idx >= NB) idx = NB - 1;
        *reinterpret_cast<float*>(sm + S_INV + i * 4) = g_inv[idx];
    }

    // fragment addressing (lane-invariant)
    const int sub  = lane >> 3;
    const int rowa_base = (FOUT == 128) ? wm * 32 : wm * 16;
    const int rowa = rowa_base + (sub & 1) * 8 + (lane & 7);
    const int csel = sub >> 1;
    const int rs   = lane & 7;
    const int lb   = lane & 15;
    const int subb = lb >> 3;
    const int rsb  = lb & 7;

    float acc[MT][NB8][4];
#pragma unroll
    for (int mt = 0; mt < MT; mt++)
#pragma unroll
        for (int nb = 0; nb < NB8; nb++)
#pragma unroll
            for (int q = 0; q < 4; q++) acc[mt][nb][q] = 0.f;

    int buf = 0;
    for (int c = 0; c < 9; c++) {
        // prefetch next chunk's B (overlaps gather + MMA)
        if (c + 1 < 9) {
            uint32_t bdst = sb + B_BASE + (buf ^ 1) * BSTEP;
            const unsigned char* shi = Bhi + (size_t)(c + 1) * TB;
            const unsigned char* slo = Blo + (size_t)(c + 1) * TB;
            for (int i = tid; i < NTB * 16; i += 512) {
                cpa16(bdst + i * 16, shi + i * 16);
                cpa16(bdst + TB + i * 16, slo + i * 16);
            }
            CP_COMMIT();
        }

        // ---- gather phase: build A chunk (128 x 128) in smem ----
        if (c == 0) {
            // self rows: direct copy, 8 independent loads in flight
#pragma unroll
            for (int j = 0; j < 8; j++) {
                int row = wid * 8 + j;
                int node = m0 + row;
                float4 v = make_float4(0.f, 0.f, 0.f, 0.f);
                if (node < n)
                    v = *reinterpret_cast<const float4*>(X + (size_t)node * 128 + lane4);
                uint32_t h0, l0, h1, l1;
                split_pack(v.x, v.y, h0, l0);
                split_pack(v.z, v.w, h1, l1);
                uint32_t off = (uint32_t)row * 256 + ((uint32_t)((lane >> 1) ^ (row & 7)) << 4)
                             + (uint32_t)(lane & 1) * 8;
                *reinterpret_cast<uint2*>(sm + A_HI + off) = make_uint2(h0, h1);
                *reinterpret_cast<uint2*>(sm + A_LO + off) = make_uint2(l0, l1);
            }
        } else {
            // relation c-1: lockstep gather, 2 groups of 4 rows for MLP
#pragma unroll
            for (int g = 0; g < 2; g++) {
                const int brow = wid * 8 + g * 4;
                int s0[4], cn[4];
                float4 a4[4];
                int mx = 0;
#pragma unroll
                for (int j = 0; j < 4; j++) {
                    int bi = (brow + j) * RREL + (c - 1);
                    int o0 = *reinterpret_cast<const int*>(sm + S_OFF + bi * 4);
                    int o1 = *reinterpret_cast<const int*>(sm + S_OFF + (bi + 1) * 4);
                    s0[j] = o0;
                    cn[j] = o1 - o0;
                    mx = max(mx, cn[j]);
                    a4[j] = make_float4(0.f, 0.f, 0.f, 0.f);
                }
                for (int k = 0; k < mx; k++) {
                    int sj[4];
#pragma unroll
                    for (int j = 0; j < 4; j++)
                        if (k < cn[j]) sj[j] = g_srcs[s0[j] + k];
#pragma unroll
                    for (int j = 0; j < 4; j++) {
                        if (k < cn[j]) {
                            const float4 v = *reinterpret_cast<const float4*>(
                                X + (size_t)sj[j] * 128 + lane4);
                            a4[j].x += v.x; a4[j].y += v.y;
                            a4[j].z += v.z; a4[j].w += v.w;
                        }
                    }
                }
#pragma unroll
                for (int j = 0; j < 4; j++) {
                    int row = brow + j;
                    float iv = *reinterpret_cast<const float*>(
                        sm + S_INV + (row * RREL + (c - 1)) * 4);
                    uint32_t h0, l0, h1, l1;
                    split_pack(a4[j].x * iv, a4[j].y * iv, h0, l0);
                    split_pack(a4[j].z * iv, a4[j].w * iv, h1, l1);
                    uint32_t off = (uint32_t)row * 256 + ((uint32_t)((lane >> 1) ^ (row & 7)) << 4)
                                 + (uint32_t)(lane & 1) * 8;
                    *reinterpret_cast<uint2*>(sm + A_HI + off) = make_uint2(h0, h1);
                    *reinterpret_cast<uint2*>(sm + A_LO + off) = make_uint2(l0, l1);
                }
            }
        }

        if (c + 1 < 9) { CP_WAIT1(); } else { CP_WAIT0(); }
        __syncthreads();   // A chunk + B chunk resident

        // ---- MMA phase: 3-product hi/lo accumulate into persistent regs ----
        const uint32_t bh_base = sb + B_BASE + buf * BSTEP;
        const uint32_t bl_base = bh_base + TB;
#pragma unroll
        for (int ks = 0; ks < 8; ks++) {
            uint32_t ca = (uint32_t)((2 * ks + csel) ^ rs) << 4;
            uint32_t ah0[4], al0[4], ah1[4], al1[4];
            ldsm4(ah0, sb + A_HI + (uint32_t)rowa * 256 + ca);
            ldsm4(al0, sb + A_LO + (uint32_t)rowa * 256 + ca);
            if (MT == 2) {
                ldsm4(ah1, sb + A_HI + (uint32_t)(rowa + 16) * 256 + ca);
                ldsm4(al1, sb + A_LO + (uint32_t)(rowa + 16) * 256 + ca);
            }
            uint32_t cb = (uint32_t)((2 * ks + subb) ^ rsb) << 4;
#pragma unroll
            for (int nb = 0; nb < NB8; nb++) {
                uint32_t rowb = (uint32_t)(wn * WNV + nb * 8 + rsb);
                uint32_t bh[2], bl[2];
                ldsm2(bh, bh_base + rowb * 256 + cb);
                ldsm2(bl, bl_base + rowb * 256 + cb);
                mma16816(acc[0][nb], ah0, bh);
                mma16816(acc[0][nb], ah0, bl);
                mma16816(acc[0][nb], al0, bh);
                if (MT == 2) {
                    mma16816(acc[1][nb], ah1, bh);
                    mma16816(acc[1][nb], ah1, bl);
                    mma16816(acc[1][nb], al1, bh);
                }
            }
        }
        __syncthreads();   // MMA done before next gather overwrites A
        buf ^= 1;
    }

    // ---- epilogue: bias (+relu), write output ----
#pragma unroll
    for (int mt = 0; mt < MT; mt++) {
        int row = m0 + rowa_base + mt * 16 + (lane >> 2);
#pragma unroll
        for (int nb = 0; nb < NB8; nb++) {
            int col = wn * WNV + nb * 8 + (lane & 3) * 2;
            float b0 = bias[col], b1 = bias[col + 1];
            float v0 = acc[mt][nb][0] + b0;
            float v1 = acc[mt][nb][1] + b1;
            float v2 = acc[mt][nb][2] + b0;
            float v3 = acc[mt][nb][3] + b1;
            if (relu) {
                v0 = fmaxf(v0, 0.f); v1 = fmaxf(v1, 0.f);
                v2 = fmaxf(v2, 0.f); v3 = fmaxf(v3, 0.f);
            }
            if (row < n)
                *reinterpret_cast<float2*>(out + (size_t)row * FOUT + col) = make_float2(v0, v1);
            if (row + 8 < n)
                *reinterpret_cast<float2*>(out + (size_t)(row + 8) * FOUT + col) = make_float2(v2, v3);
        }
    }
}

// ---------------- host ----------------
extern "C" void kernel_launch(void* const* d_in, const int* in_sizes, int n_in,
                              void* d_out, int out_size) {
    const float* x  = (const float*)d_in[0];
    const int* eidx = (const int*)d_in[1];
    const int* et   = (const int*)d_in[2];
    const float* w0 = (const float*)d_in[3];
    const float* r0 = (const float*)d_in[4];
    const float* b0 = (const float*)d_in[5];
    const float* w1 = (const float*)d_in[6];
    const float* r1 = (const float*)d_in[7];
    const float* b1 = (const float*)d_in[8];
    const float* w2 = (const float*)d_in[9];
    const float* r2 = (const float*)d_in[10];
    const float* b2 = (const float*)d_in[11];
    float* out = (float*)d_out;

    int n = in_sizes[0] / FIN;   // 50000
    int e = in_sizes[2];         // 800000
    const int* src = eidx;
    const int* dst = eidx + e;

    float *h0, *h1;
    unsigned char *B0hi, *B0lo, *B1hi, *B1lo, *B2hi, *B2lo;
    cudaGetSymbolAddress((void**)&h0, g_h0);
    cudaGetSymbolAddress((void**)&h1, g_h1);
    cudaGetSymbolAddress((void**)&B0hi, g_B0hi);
    cudaGetSymbolAddress((void**)&B0lo, g_B0lo);
    cudaGetSymbolAddress((void**)&B1hi, g_B1hi);
    cudaGetSymbolAddress((void**)&B1lo, g_B1lo);
    cudaGetSymbolAddress((void**)&B2hi, g_B2hi);
    cudaGetSymbolAddress((void**)&B2lo, g_B2lo);

    // smem: A(64K) + 2 B bufs + off table(4352) + inv table(4096)
    const int SMEM128 = 65536 + 2 * (2 * 128 * 256) + 4352 + 4096;   // 205056
    const int SMEM16  = 65536 + 2 * (2 * 16 * 256) + 4352 + 4096;    // 90368
    cudaFuncSetAttribute(rgcn_fused_k<128>, cudaFuncAttributeMaxDynamicSharedMemorySize, SMEM128);
    cudaFuncSetAttribute(rgcn_fused_k<16>,  cudaFuncAttributeMaxDynamicSharedMemorySize, SMEM16);

    // Weight image precompute (independent of graph build)
    conv_b_k<128><<<(9 * 16 * 128 + 255) / 256, 256>>>(r0, w0, B0hi, B0lo);
    conv_b_k<128><<<(9 * 16 * 128 + 255) / 256, 256>>>(r1, w1, B1hi, B1lo);
    conv_b_k<16><<<(9 * 16 * 16 + 255) / 256, 256>>>(r2, w2, B2hi, B2lo);

    // CSR build (edge structure shared by all 3 layers)
    zero_cnt_k<<<(NB + 255) / 256, 256>>>();
    count_k<<<(e + 255) / 256, 256>>>(dst, et, e);
    scan1_k<<<SCAN_NBLK, SCAN_T>>>();
    scan2_k<<<1, SCAN_T>>>();
    scan3_k<<<(NB + 255) / 256, 256>>>(e);
    fill_k<<<(e + 255) / 256, 256>>>(src, dst, et, e);

    int mblocks = (n + 127) / 128;   // 391
    // Fully-fused layers: gather(+mean) -> GEMM -> bias/relu, no Y materialization
    rgcn_fused_k<128><<<mblocks, 512, SMEM128>>>(x,  B0hi, B0lo, b0, h0, n, 1);
    rgcn_fused_k<128><<<mblocks, 512, SMEM128>>>(h0, B1hi, B1lo, b1, h1, n, 1);
    rgcn_fused_k<16><<<mblocks, 512, SMEM16>>>(h1, B2hi, B2lo, b2, out, n, 0);
}

// round 11
// speedup vs baseline: 1.3216x; 1.1351x over previous
#include <cuda_runtime.h>
#include <cuda_bf16.h>
#include <cstdint>

// Problem constants (fixed dataset)
#define NMAX 50000
#define RREL 8
#define FIN  128
#define NB   (NMAX * RREL)          // 400000 segment bins
#define EMAX 800000

// ---------------- device scratch (allocation-free) ----------------
__device__ float g_h0[NMAX * FIN];
__device__ float g_h1[NMAX * FIN];
__device__ int   g_cnt[NB];
__device__ int   g_off[NB + 64];
__device__ int   g_cur[NB];
__device__ int   g_srcs[EMAX + 64];
__device__ float g_inv[NB];
__device__ int   g_bsum[256];
// Pre-split, pre-swizzled B chunk images (hi/lo) per layer
__device__ unsigned char g_B0hi[294912];
__device__ unsigned char g_B0lo[294912];
__device__ unsigned char g_B1hi[294912];
__device__ unsigned char g_B1lo[294912];
__device__ unsigned char g_B2hi[36864];
__device__ unsigned char g_B2lo[36864];

// ---------------- PTX helpers (baseline sm_80-level, no 'a' features) ----------
__device__ __forceinline__ uint32_t smem_u32(const void* p) {
    uint32_t a;
    asm("{ .reg .u64 t; cvta.to.shared.u64 t, %1; cvt.u32.u64 %0, t; }" : "=r"(a) : "l"(p));
    return a;
}
__device__ __forceinline__ void ldsm4(uint32_t* r, uint32_t addr) {
    asm volatile("ldmatrix.sync.aligned.m8n8.x4.shared.b16 {%0,%1,%2,%3}, [%4];"
                 : "=r"(r[0]), "=r"(r[1]), "=r"(r[2]), "=r"(r[3]) : "r"(addr));
}
__device__ __forceinline__ void ldsm2(uint32_t* r, uint32_t addr) {
    asm volatile("ldmatrix.sync.aligned.m8n8.x2.shared.b16 {%0,%1}, [%2];"
                 : "=r"(r[0]), "=r"(r[1]) : "r"(addr));
}
__device__ __forceinline__ void mma16816(float* c, const uint32_t* a, const uint32_t* b) {
    asm volatile("mma.sync.aligned.m16n8k16.row.col.f32.bf16.bf16.f32 "
                 "{%0,%1,%2,%3}, {%4,%5,%6,%7}, {%8,%9}, {%0,%1,%2,%3};"
                 : "+f"(c[0]), "+f"(c[1]), "+f"(c[2]), "+f"(c[3])
                 : "r"(a[0]), "r"(a[1]), "r"(a[2]), "r"(a[3]), "r"(b[0]), "r"(b[1]));
}
__device__ __forceinline__ void cpa16(uint32_t smem, const void* g) {
    asm volatile("cp.async.cg.shared.global [%0], [%1], 16;" :: "r"(smem), "l"(g));
}
#define CP_COMMIT() asm volatile("cp.async.commit_group;" ::: "memory")
#define CP_WAIT0()  asm volatile("cp.async.wait_group 0;" ::: "memory")

// hi/lo bf16 split + pack pair into one u32 (low half = first element)
__device__ __forceinline__ void split_pack(float a, float b, uint32_t& hi, uint32_t& lo) {
    __nv_bfloat16 ah = __float2bfloat16(a), bh = __float2bfloat16(b);
    __nv_bfloat162 hh; hh.x = ah; hh.y = bh;
    hi = *reinterpret_cast<uint32_t*>(&hh);
    __nv_bfloat162 ll;
    ll.x = __float2bfloat16(a - __bfloat162float(ah));
    ll.y = __float2bfloat16(b - __bfloat162float(bh));
    lo = *reinterpret_cast<uint32_t*>(&ll);
}

// ---------------- CSR build ----------------
__global__ void zero_cnt_k() {
    int i = blockIdx.x * blockDim.x + threadIdx.x;
    if (i < NB) g_cnt[i] = 0;
}
__global__ void count_k(const int* __restrict__ dst, const int* __restrict__ et, int e) {
    int i = blockIdx.x * blockDim.x + threadIdx.x;
    if (i < e) atomicAdd(&g_cnt[dst[i] * RREL + et[i]], 1);
}

#define SCAN_T 256
#define SCAN_I 8
#define SCAN_E (SCAN_T * SCAN_I)                 // 2048
#define SCAN_NBLK ((NB + SCAN_E - 1) / SCAN_E)   // 196

__global__ void scan1_k() {
    __shared__ int sh[SCAN_T];
    int b = blockIdx.x, t = threadIdx.x;
    int base = b * SCAN_E + t * SCAN_I;
    int v[SCAN_I]; int s = 0;
#pragma unroll
    for (int i = 0; i < SCAN_I; i++) {
        int idx = base + i;
        v[i] = (idx < NB) ? g_cnt[idx] : 0;
        s += v[i];
    }
    sh[t] = s; __syncthreads();
    for (int off = 1; off < SCAN_T; off <<= 1) {
        int x = (t >= off) ? sh[t - off] : 0;
        __syncthreads();
        sh[t] += x;
        __syncthreads();
    }
    if (t == SCAN_T - 1) g_bsum[b] = sh[t];
    int excl = sh[t] - s;
#pragma unroll
    for (int i = 0; i < SCAN_I; i++) {
        int idx = base + i;
        if (idx < NB) g_off[idx] = excl;
        excl += v[i];
    }
}
__global__ void scan2_k() {
    __shared__ int sh[SCAN_T];
    int t = threadIdx.x;
    int v = (t < SCAN_NBLK) ? g_bsum[t] : 0;
    sh[t] = v; __syncthreads();
    for (int off = 1; off < SCAN_T; off <<= 1) {
        int x = (t >= off) ? sh[t - off] : 0;
        __syncthreads();
        sh[t] += x;
        __syncthreads();
    }
    if (t < SCAN_NBLK) g_bsum[t] = sh[t] - v;
}
__global__ void scan3_k(int e) {
    int i = blockIdx.x * blockDim.x + threadIdx.x;
    if (i < NB) {
        int o = g_off[i] + g_bsum[i / SCAN_E];
        g_off[i] = o;
        g_cur[i] = o;
        int c = g_cnt[i];
        g_inv[i] = 1.0f / (float)(c > 1 ? c : 1);
    }
    if (i == 0) g_off[NB] = e;
}
__global__ void fill_k(const int* __restrict__ src, const int* __restrict__ dst,
                       const int* __restrict__ et, int e) {
    int i = blockIdx.x * blockDim.x + threadIdx.x;
    if (i < e) {
        int bin = dst[i] * RREL + et[i];
        int slot = atomicAdd(&g_cur[bin], 1);
        g_srcs[slot] = src[i];
    }
}

// ---------------- B precompute: split + swizzle weight chunk images ------------
template<int FOUT>
__global__ void conv_b_k(const float* __restrict__ root, const float* __restrict__ W,
                         unsigned char* __restrict__ Dhi, unsigned char* __restrict__ Dlo) {
    constexpr int NTB = (FOUT == 128) ? 128 : 16;
    int i = blockIdx.x * blockDim.x + threadIdx.x;
    if (i >= 9 * 16 * NTB) return;
    int t = i / (16 * NTB);
    int j = i % (16 * NTB);
    int cc = j / NTB, ln = j % NTB;
    float v[8];
#pragma unroll
    for (int kk = 0; kk < 8; kk++) {
        int k = cc * 8 + kk;
        v[kk] = (t == 0) ? root[k * FOUT + ln]
                         : W[((size_t)(t - 1) * 128 + k) * FOUT + ln];
    }
    uint32_t hi[4], lo[4];
#pragma unroll
    for (int q = 0; q < 4; q++) split_pack(v[2*q], v[2*q+1], hi[q], lo[q]);
    uint32_t off = (uint32_t)t * (NTB * 256) + (uint32_t)ln * 256 + ((uint32_t)(cc ^ (ln & 7)) << 4);
    *reinterpret_cast<uint4*>(Dhi + off) = make_uint4(hi[0], hi[1], hi[2], hi[3]);
    *reinterpret_cast<uint4*>(Dlo + off) = make_uint4(lo[0], lo[1], lo[2], lo[3]);
}

// ---------------- fully-fused RGCN layer, M=64 tile, 2 CTAs/SM -----------------
// out[node] = (relu)( X[node]@root + bias + sum_r mean_{src in N_r}(X[src]) @ W_r )
// 256 threads = 8 warps, 64 nodes/block. Cross-CTA overlap hides gather latency.
template<int FOUT>
__global__ void __launch_bounds__(256, 2)
rgcn_fused_k(const float* __restrict__ X,
             const unsigned char* __restrict__ Bhi,
             const unsigned char* __restrict__ Blo,
             const float* __restrict__ bias,
             float* __restrict__ out, int n, int relu) {
    constexpr int NTB = (FOUT == 128) ? 128 : 16;
    constexpr int WNV = (FOUT == 128) ? 32 : 8;   // warp N span
    constexpr int NB8 = WNV / 8;                  // 4 or 1
    constexpr int MT  = (FOUT == 128) ? 2 : 1;    // 16-row m-subtiles per warp
    constexpr int TB  = NTB * 256;                // chunk image bytes (hi or lo)
    constexpr int A_HI = 0, A_LO = 16384, B_BASE = 32768;
    constexpr int S_OFF = B_BASE + 2 * TB;        // 513 ints
    constexpr int S_INV = S_OFF + 2176;           // 512 floats

    extern __shared__ char sm[];
    const uint32_t sb = smem_u32(sm);
    const int tid = threadIdx.x, lane = tid & 31, wid = tid >> 5;
    const int wm = (FOUT == 128) ? (wid & 1) : (wid >> 1);   // 2 or 4 m-tiles
    const int wn = (FOUT == 128) ? (wid >> 1) : (wid & 1);   // 4 or 2 n-tiles
    const int m0 = blockIdx.x * 64;
    const int lane4 = lane * 4;

    // prologue: issue B(0) copy
    for (int i = tid; i < NTB * 16; i += 256) {
        cpa16(sb + B_BASE + i * 16, Bhi + i * 16);
        cpa16(sb + B_BASE + TB + i * 16, Blo + i * 16);
    }
    CP_COMMIT();

    // stage CSR offsets (+ sentinel) and inverse-degree weights into smem
    for (int i = tid; i < 513; i += 256) {
        int idx = m0 * RREL + i;
        if (idx > NB) idx = NB;
        *reinterpret_cast<int*>(sm + S_OFF + i * 4) = g_off[idx];
    }
    for (int i = tid; i < 512; i += 256) {
        int idx = m0 * RREL + i;
        if (idx >= NB) idx = NB - 1;
        *reinterpret_cast<float*>(sm + S_INV + i * 4) = g_inv[idx];
    }

    // fragment addressing (lane-invariant)
    const int sub  = lane >> 3;
    const int rowa_base = (FOUT == 128) ? wm * 32 : wm * 16;
    const int rowa = rowa_base + (sub & 1) * 8 + (lane & 7);
    const int csel = sub >> 1;
    const int rs   = lane & 7;
    const int lb   = lane & 15;
    const int subb = lb >> 3;
    const int rsb  = lb & 7;

    float acc[MT][NB8][4];
#pragma unroll
    for (int mt = 0; mt < MT; mt++)
#pragma unroll
        for (int nb = 0; nb < NB8; nb++)
#pragma unroll
            for (int q = 0; q < 4; q++) acc[mt][nb][q] = 0.f;

    for (int c = 0; c < 9; c++) {
        // ---- gather phase: build A chunk (64 x 128) in smem, 8 rows per warp ----
        if (c == 0) {
#pragma unroll
            for (int j = 0; j < 8; j++) {
                int row = wid * 8 + j;
                int node = m0 + row;
                float4 v = make_float4(0.f, 0.f, 0.f, 0.f);
                if (node < n)
                    v = *reinterpret_cast<const float4*>(X + (size_t)node * 128 + lane4);
                uint32_t h0, l0, h1, l1;
                split_pack(v.x, v.y, h0, l0);
                split_pack(v.z, v.w, h1, l1);
                uint32_t off = (uint32_t)row * 256 + ((uint32_t)((lane >> 1) ^ (row & 7)) << 4)
                             + (uint32_t)(lane & 1) * 8;
                *reinterpret_cast<uint2*>(sm + A_HI + off) = make_uint2(h0, h1);
                *reinterpret_cast<uint2*>(sm + A_LO + off) = make_uint2(l0, l1);
            }
        } else {
            // relation c-1: lockstep gather, 2 groups of 4 rows for MLP
#pragma unroll
            for (int g = 0; g < 2; g++) {
                const int brow = wid * 8 + g * 4;
                int s0[4], cn[4];
                float4 a4[4];
                int mx = 0;
#pragma unroll
                for (int j = 0; j < 4; j++) {
                    int bi = (brow + j) * RREL + (c - 1);
                    int o0 = *reinterpret_cast<const int*>(sm + S_OFF + bi * 4);
                    int o1 = *reinterpret_cast<const int*>(sm + S_OFF + (bi + 1) * 4);
                    s0[j] = o0;
                    cn[j] = o1 - o0;
                    mx = max(mx, cn[j]);
                    a4[j] = make_float4(0.f, 0.f, 0.f, 0.f);
                }
                for (int k = 0; k < mx; k++) {
                    int sj[4];
#pragma unroll
                    for (int j = 0; j < 4; j++)
                        if (k < cn[j]) sj[j] = g_srcs[s0[j] + k];
#pragma unroll
                    for (int j = 0; j < 4; j++) {
                        if (k < cn[j]) {
                            const float4 v = *reinterpret_cast<const float4*>(
                                X + (size_t)sj[j] * 128 + lane4);
                            a4[j].x += v.x; a4[j].y += v.y;
                            a4[j].z += v.z; a4[j].w += v.w;
                        }
                    }
                }
#pragma unroll
                for (int j = 0; j < 4; j++) {
                    int row = brow + j;
                    float iv = *reinterpret_cast<const float*>(
                        sm + S_INV + (row * RREL + (c - 1)) * 4);
                    uint32_t h0, l0, h1, l1;
                    split_pack(a4[j].x * iv, a4[j].y * iv, h0, l0);
                    split_pack(a4[j].z * iv, a4[j].w * iv, h1, l1);
                    uint32_t off = (uint32_t)row * 256 + ((uint32_t)((lane >> 1) ^ (row & 7)) << 4)
                                 + (uint32_t)(lane & 1) * 8;
                    *reinterpret_cast<uint2*>(sm + A_HI + off) = make_uint2(h0, h1);
                    *reinterpret_cast<uint2*>(sm + A_LO + off) = make_uint2(l0, l1);
                }
            }
        }

        CP_WAIT0();
        __syncthreads();   // A chunk + B chunk resident

        // ---- MMA phase: 3-product hi/lo accumulate into persistent regs ----
        const uint32_t bh_base = sb + B_BASE;
        const uint32_t bl_base = bh_base + TB;
#pragma unroll
        for (int ks = 0; ks < 8; ks++) {
            uint32_t ca = (uint32_t)((2 * ks + csel) ^ rs) << 4;
            uint32_t ah0[4], al0[4], ah1[4], al1[4];
            ldsm4(ah0, sb + A_HI + (uint32_t)rowa * 256 + ca);
            ldsm4(al0, sb + A_LO + (uint32_t)rowa * 256 + ca);
            if (MT == 2) {
                ldsm4(ah1, sb + A_HI + (uint32_t)(rowa + 16) * 256 + ca);
                ldsm4(al1, sb + A_LO + (uint32_t)(rowa + 16) * 256 + ca);
            }
            uint32_t cb = (uint32_t)((2 * ks + subb) ^ rsb) << 4;
#pragma unroll
            for (int nb = 0; nb < NB8; nb++) {
                uint32_t rowb = (uint32_t)(wn * WNV + nb * 8 + rsb);
                uint32_t bh[2], bl[2];
                ldsm2(bh, bh_base + rowb * 256 + cb);
                ldsm2(bl, bl_base + rowb * 256 + cb);
                mma16816(acc[0][nb], ah0, bh);
                mma16816(acc[0][nb], ah0, bl);
                mma16816(acc[0][nb], al0, bh);
                if (MT == 2) {
                    mma16816(acc[1][nb], ah1, bh);
                    mma16816(acc[1][nb], ah1, bl);
                    mma16816(acc[1][nb], al1, bh);
                }
            }
        }
        __syncthreads();   // all warps done with A(c) and B(c)

        // issue next chunk's B copy (single buffer — safe after sync);
        // overlaps the next gather phase
        if (c + 1 < 9) {
            const unsigned char* shi = Bhi + (size_t)(c + 1) * TB;
            const unsigned char* slo = Blo + (size_t)(c + 1) * TB;
            for (int i = tid; i < NTB * 16; i += 256) {
                cpa16(sb + B_BASE + i * 16, shi + i * 16);
                cpa16(sb + B_BASE + TB + i * 16, slo + i * 16);
            }
            CP_COMMIT();
        }
    }

    // ---- epilogue: bias (+relu), write output ----
#pragma unroll
    for (int mt = 0; mt < MT; mt++) {
        int row = m0 + rowa_base + mt * 16 + (lane >> 2);
#pragma unroll
        for (int nb = 0; nb < NB8; nb++) {
            int col = wn * WNV + nb * 8 + (lane & 3) * 2;
            float b0 = bias[col], b1 = bias[col + 1];
            float v0 = acc[mt][nb][0] + b0;
            float v1 = acc[mt][nb][1] + b1;
            float v2 = acc[mt][nb][2] + b0;
            float v3 = acc[mt][nb][3] + b1;
            if (relu) {
                v0 = fmaxf(v0, 0.f); v1 = fmaxf(v1, 0.f);
                v2 = fmaxf(v2, 0.f); v3 = fmaxf(v3, 0.f);
            }
            if (row < n)
                *reinterpret_cast<float2*>(out + (size_t)row * FOUT + col) = make_float2(v0, v1);
            if (row + 8 < n)
                *reinterpret_cast<float2*>(out + (size_t)(row + 8) * FOUT + col) = make_float2(v2, v3);
        }
    }
}

// ---------------- host ----------------
extern "C" void kernel_launch(void* const* d_in, const int* in_sizes, int n_in,
                              void* d_out, int out_size) {
    const float* x  = (const float*)d_in[0];
    const int* eidx = (const int*)d_in[1];
    const int* et   = (const int*)d_in[2];
    const float* w0 = (const float*)d_in[3];
    const float* r0 = (const float*)d_in[4];
    const float* b0 = (const float*)d_in[5];
    const float* w1 = (const float*)d_in[6];
    const float* r1 = (const float*)d_in[7];
    const float* b1 = (const float*)d_in[8];
    const float* w2 = (const float*)d_in[9];
    const float* r2 = (const float*)d_in[10];
    const float* b2 = (const float*)d_in[11];
    float* out = (float*)d_out;

    int n = in_sizes[0] / FIN;   // 50000
    int e = in_sizes[2];         // 800000
    const int* src = eidx;
    const int* dst = eidx + e;

    float *h0, *h1;
    unsigned char *B0hi, *B0lo, *B1hi, *B1lo, *B2hi, *B2lo;
    cudaGetSymbolAddress((void**)&h0, g_h0);
    cudaGetSymbolAddress((void**)&h1, g_h1);
    cudaGetSymbolAddress((void**)&B0hi, g_B0hi);
    cudaGetSymbolAddress((void**)&B0lo, g_B0lo);
    cudaGetSymbolAddress((void**)&B1hi, g_B1hi);
    cudaGetSymbolAddress((void**)&B1lo, g_B1lo);
    cudaGetSymbolAddress((void**)&B2hi, g_B2hi);
    cudaGetSymbolAddress((void**)&B2lo, g_B2lo);

    // smem: A(32K) + B hi/lo single buf + off(2176) + inv(2048)
    const int SMEM128 = 32768 + 2 * (128 * 256) + 2176 + 2048;   // 102528 -> 2 CTAs/SM
    const int SMEM16  = 32768 + 2 * (16 * 256) + 2176 + 2048;    // 45184
    cudaFuncSetAttribute(rgcn_fused_k<128>, cudaFuncAttributeMaxDynamicSharedMemorySize, SMEM128);
    cudaFuncSetAttribute(rgcn_fused_k<16>,  cudaFuncAttributeMaxDynamicSharedMemorySize, SMEM16);

    // Weight image precompute (independent of graph build)
    conv_b_k<128><<<(9 * 16 * 128 + 255) / 256, 256>>>(r0, w0, B0hi, B0lo);
    conv_b_k<128><<<(9 * 16 * 128 + 255) / 256, 256>>>(r1, w1, B1hi, B1lo);
    conv_b_k<16><<<(9 * 16 * 16 + 255) / 256, 256>>>(r2, w2, B2hi, B2lo);

    // CSR build (edge structure shared by all 3 layers)
    zero_cnt_k<<<(NB + 255) / 256, 256>>>();
    count_k<<<(e + 255) / 256, 256>>>(dst, et, e);
    scan1_k<<<SCAN_NBLK, SCAN_T>>>();
    scan2_k<<<1, SCAN_T>>>();
    scan3_k<<<(NB + 255) / 256, 256>>>(e);
    fill_k<<<(e + 255) / 256, 256>>>(src, dst, et, e);

    int mblocks = (n + 63) / 64;   // 782
    // Fully-fused layers: gather(+mean) -> GEMM -> bias/relu, no Y materialization
    rgcn_fused_k<128><<<mblocks, 256, SMEM128>>>(x,  B0hi, B0lo, b0, h0, n, 1);
    rgcn_fused_k<128><<<mblocks, 256, SMEM128>>>(h0, B1hi, B1lo, b1, h1, n, 1);
    rgcn_fused_k<16><<<mblocks, 256, SMEM16>>>(h1, B2hi, B2lo, b2, out, n, 0);
}

// round 13
// speedup vs baseline: 1.6525x; 1.2504x over previous
#include <cuda_runtime.h>
#include <cuda_bf16.h>
#include <cuda_fp16.h>
#include <cstdint>

// Problem constants (fixed dataset)
#define NMAX 50000
#define RREL 8
#define FIN  128
#define NB   (NMAX * RREL)          // 400000 segment bins
#define CS   ((size_t)NMAX * 128)   // Y chunk stride (elements)
#define EMAX 800000

// ---------------- device scratch (allocation-free) ----------------
__device__ __half g_Yh[9 * NMAX * 128];  // GEMM output: fp16 for H layers (115MB, L2-resident);
                                         // reused as f32 [node][144] for layer 2 (28.8MB)
__device__ float g_h0[NMAX * FIN];
__device__ float g_h1[NMAX * FIN];
__device__ int   g_cnt[NB];
__device__ int   g_off[NB + 64];
__device__ int   g_cur[NB];
__device__ int   g_srcs[EMAX + 64];     // packed: src | (rel << 20)
__device__ float g_wt[EMAX + 64];       // per-edge 1/deg weight
__device__ float g_inv[NB];
__device__ int   g_bsum[256];
// Pre-split, pre-swizzled B images (hi/lo)
__device__ unsigned char g_Bhi[294912];
__device__ unsigned char g_Blo[294912];

// ---------------- PTX helpers (baseline sm_80-level, no 'a' features) ----------
__device__ __forceinline__ uint32_t smem_u32(const void* p) {
    uint32_t a;
    asm("{ .reg .u64 t; cvta.to.shared.u64 t, %1; cvt.u32.u64 %0, t; }" : "=r"(a) : "l"(p));
    return a;
}
__device__ __forceinline__ void ldsm4(uint32_t* r, uint32_t addr) {
    asm volatile("ldmatrix.sync.aligned.m8n8.x4.shared.b16 {%0,%1,%2,%3}, [%4];"
                 : "=r"(r[0]), "=r"(r[1]), "=r"(r[2]), "=r"(r[3]) : "r"(addr));
}
__device__ __forceinline__ void ldsm2(uint32_t* r, uint32_t addr) {
    asm volatile("ldmatrix.sync.aligned.m8n8.x2.shared.b16 {%0,%1}, [%2];"
                 : "=r"(r[0]), "=r"(r[1]) : "r"(addr));
}
__device__ __forceinline__ void mma16816(float* c, const uint32_t* a, const uint32_t* b) {
    asm volatile("mma.sync.aligned.m16n8k16.row.col.f32.bf16.bf16.f32 "
                 "{%0,%1,%2,%3}, {%4,%5,%6,%7}, {%8,%9}, {%0,%1,%2,%3};"
                 : "+f"(c[0]), "+f"(c[1]), "+f"(c[2]), "+f"(c[3])
                 : "r"(a[0]), "r"(a[1]), "r"(a[2]), "r"(a[3]), "r"(b[0]), "r"(b[1]));
}
__device__ __forceinline__ void cpa16(uint32_t smem, const void* g) {
    asm volatile("cp.async.cg.shared.global [%0], [%1], 16;" :: "r"(smem), "l"(g));
}
#define CP_COMMIT() asm volatile("cp.async.commit_group;" ::: "memory")
#define CP_WAIT0()  asm volatile("cp.async.wait_group 0;" ::: "memory")

// hi/lo bf16 split + pack pair into one u32 (low half = first element)
__device__ __forceinline__ void split_pack(float a, float b, uint32_t& hi, uint32_t& lo) {
    __nv_bfloat16 ah = __float2bfloat16(a), bh = __float2bfloat16(b);
    __nv_bfloat162 hh; hh.x = ah; hh.y = bh;
    hi = *reinterpret_cast<uint32_t*>(&hh);
    __nv_bfloat162 ll;
    ll.x = __float2bfloat16(a - __bfloat162float(ah));
    ll.y = __float2bfloat16(b - __bfloat162float(bh));
    lo = *reinterpret_cast<uint32_t*>(&ll);
}

// ---------------- CSR build ----------------
__global__ void zero_cnt_k() {
    int i = blockIdx.x * blockDim.x + threadIdx.x;
    if (i < NB) g_cnt[i] = 0;
}
__global__ void count_k(const int* __restrict__ dst, const int* __restrict__ et, int e) {
    int i = blockIdx.x * blockDim.x + threadIdx.x;
    if (i < e) atomicAdd(&g_cnt[dst[i] * RREL + et[i]], 1);
}

#define SCAN_T 256
#define SCAN_I 8
#define SCAN_E (SCAN_T * SCAN_I)                 // 2048
#define SCAN_NBLK ((NB + SCAN_E - 1) / SCAN_E)   // 196

__global__ void scan1_k() {
    __shared__ int sh[SCAN_T];
    int b = blockIdx.x, t = threadIdx.x;
    int base = b * SCAN_E + t * SCAN_I;
    int v[SCAN_I]; int s = 0;
#pragma unroll
    for (int i = 0; i < SCAN_I; i++) {
        int idx = base + i;
        v[i] = (idx < NB) ? g_cnt[idx] : 0;
        s += v[i];
    }
    sh[t] = s; __syncthreads();
    for (int off = 1; off < SCAN_T; off <<= 1) {
        int x = (t >= off) ? sh[t - off] : 0;
        __syncthreads();
        sh[t] += x;
        __syncthreads();
    }
    if (t == SCAN_T - 1) g_bsum[b] = sh[t];
    int excl = sh[t] - s;
#pragma unroll
    for (int i = 0; i < SCAN_I; i++) {
        int idx = base + i;
        if (idx < NB) g_off[idx] = excl;
        excl += v[i];
    }
}
__global__ void scan2_k() {
    __shared__ int sh[SCAN_T];
    int t = threadIdx.x;
    int v = (t < SCAN_NBLK) ? g_bsum[t] : 0;
    sh[t] = v; __syncthreads();
    for (int off = 1; off < SCAN_T; off <<= 1) {
        int x = (t >= off) ? sh[t - off] : 0;
        __syncthreads();
        sh[t] += x;
        __syncthreads();
    }
    if (t < SCAN_NBLK) g_bsum[t] = sh[t] - v;
}
__global__ void scan3_k(int e) {
    int i = blockIdx.x * blockDim.x + threadIdx.x;
    if (i < NB) {
        int o = g_off[i] + g_bsum[i / SCAN_E];
        g_off[i] = o;
        g_cur[i] = o;
        int c = g_cnt[i];
        g_inv[i] = 1.0f / (float)(c > 1 ? c : 1);
    }
    if (i == 0) g_off[NB] = e;
}
__global__ void fill_k(const int* __restrict__ src, const int* __restrict__ dst,
                       const int* __restrict__ et, int e) {
    int i = blockIdx.x * blockDim.x + threadIdx.x;
    if (i < e) {
        int t = et[i];
        int bin = dst[i] * RREL + t;
        int slot = atomicAdd(&g_cur[bin], 1);
        g_srcs[slot] = src[i] | (t << 20);
        g_wt[slot] = g_inv[bin];
    }
}

// ---------------- B precompute: split + swizzle weight images into global ------
template<int FOUT>
__global__ void conv_b_k(const float* __restrict__ root, const float* __restrict__ W) {
    constexpr int NT  = (FOUT == 128) ? 128 : 144;
    constexpr int TOT = (FOUT == 128) ? 9 : 1;
    int i = blockIdx.x * blockDim.x + threadIdx.x;
    if (i >= TOT * 16 * NT) return;
    int t = i / (16 * NT);
    int j = i % (16 * NT);
    int c = j / NT, ln = j % NT;
    float v[8];
#pragma unroll
    for (int kk = 0; kk < 8; kk++) {
        int k = c * 8 + kk;
        if (FOUT == 128)
            v[kk] = (t == 0) ? root[k * 128 + ln]
                             : W[((size_t)(t - 1) * 128 + k) * 128 + ln];
        else
            v[kk] = (ln < 16) ? root[k * 16 + ln]
                              : W[((size_t)((ln - 16) >> 4) * 128 + k) * 16 + ((ln - 16) & 15)];
    }
    uint32_t hi[4], lo[4];
#pragma unroll
    for (int q = 0; q < 4; q++) split_pack(v[2*q], v[2*q+1], hi[q], lo[q]);
    uint32_t off = (uint32_t)t * (NT * 256) + (uint32_t)ln * 256 + ((uint32_t)(c ^ (ln & 7)) << 4);
    *reinterpret_cast<uint4*>(g_Bhi + off) = make_uint4(hi[0], hi[1], hi[2], hi[3]);
    *reinterpret_cast<uint4*>(g_Blo + off) = make_uint4(lo[0], lo[1], lo[2], lo[3]);
}

// ---------------- HMMA GEMM: Y = X @ [root | W0..W7], hi/lo bf16 split --------
// FOUT=128: 9 N-tiles of 128, Y stored fp16, chunked [tile][node][128]
// FOUT=16 : single N-tile of 144, Y stored f32 row-major [node][144]
template<int FOUT>
__global__ void __launch_bounds__(256, 1) gemm_mma_k(const float* __restrict__ X,
                                                     void* __restrict__ Yout, int n) {
    constexpr int NT    = (FOUT == 128) ? 128 : 144;
    constexpr int TILES = (FOUT == 128) ? 3 : 1;
    constexpr int WN    = NT / 2;                     // warp N span (64 or 72)
    constexpr int NB8   = WN / 8;                     // 8 or 9
    constexpr int TB    = NT * 256;                   // tile image bytes (hi or lo)
    constexpr int A_HI = 0, A_LO = 32768, B_BASE = 65536, BSTEP = 2 * TB;

    extern __shared__ char sm[];
    const uint32_t sb = smem_u32(sm);
    const int tid = threadIdx.x, lane = tid & 31, wid = tid >> 5;
    const int wm = wid & 3, wn = wid >> 2;
    const int m0 = blockIdx.x * 128;
    const int t0 = blockIdx.y * TILES;

    // kick off B copy for first tile into buf 0
    {
        uint32_t b0 = sb + B_BASE;
        const unsigned char* shi = g_Bhi + (size_t)t0 * TB;
        const unsigned char* slo = g_Blo + (size_t)t0 * TB;
        for (int i = tid; i < NT * 16; i += 256) {
            cpa16(b0 + i * 16, shi + i * 16);
            cpa16(b0 + TB + i * 16, slo + i * 16);
        }
        CP_COMMIT();
    }

    // A conversion (overlaps B copy)
    for (int i = tid; i < 128 * 16; i += 256) {
        int row = i >> 4, c = i & 15;
        int g = m0 + row;
        float v[8];
        if (g < n) {
            const float4* p = reinterpret_cast<const float4*>(X + (size_t)g * 128 + c * 8);
            float4 f0 = p[0], f1 = p[1];
            v[0]=f0.x; v[1]=f0.y; v[2]=f0.z; v[3]=f0.w; v[4]=f1.x; v[5]=f1.y; v[6]=f1.z; v[7]=f1.w;
        } else {
#pragma unroll
            for (int j = 0; j < 8; j++) v[j] = 0.f;
        }
        uint32_t hi[4], lo[4];
#pragma unroll
        for (int j = 0; j < 4; j++) split_pack(v[2*j], v[2*j+1], hi[j], lo[j]);
        uint32_t off = (uint32_t)row * 256 + ((uint32_t)(c ^ (row & 7)) << 4);
        *reinterpret_cast<uint4*>(sm + A_HI + off) = make_uint4(hi[0], hi[1], hi[2], hi[3]);
        *reinterpret_cast<uint4*>(sm + A_LO + off) = make_uint4(lo[0], lo[1], lo[2], lo[3]);
    }

    // lane-invariant ldmatrix addressing
    const int sub  = lane >> 3;
    const int rowa = wm * 32 + (sub & 1) * 8 + (lane & 7);
    const int csel = sub >> 1;
    const int rs   = lane & 7;
    const int lb   = lane & 15;
    const int subb = lb >> 3;
    const int rsb  = lb & 7;

    int buf = 0;
    for (int it = 0; it < TILES; it++) {
        const int t = t0 + it;
        CP_WAIT0();
        __syncthreads();

        if (it + 1 < TILES) {
            uint32_t bn = sb + B_BASE + (buf ^ 1) * BSTEP;
            const unsigned char* shi = g_Bhi + (size_t)(t + 1) * TB;
            const unsigned char* slo = g_Blo + (size_t)(t + 1) * TB;
            for (int i = tid; i < NT * 16; i += 256) {
                cpa16(bn + i * 16, shi + i * 16);
                cpa16(bn + TB + i * 16, slo + i * 16);
            }
            CP_COMMIT();
        }

        const uint32_t bh_base = sb + B_BASE + buf * BSTEP;
        const uint32_t bl_base = bh_base + TB;

        float acc[2][NB8][4];
#pragma unroll
        for (int mt = 0; mt < 2; mt++)
#pragma unroll
            for (int nb = 0; nb < NB8; nb++)
#pragma unroll
                for (int j = 0; j < 4; j++) acc[mt][nb][j] = 0.f;

#pragma unroll
        for (int ks = 0; ks < 8; ks++) {
            uint32_t ca = (uint32_t)((2 * ks + csel) ^ rs) << 4;
            uint32_t ah0[4], ah1[4], al0[4], al1[4];
            ldsm4(ah0, sb + A_HI + (uint32_t)rowa * 256 + ca);
            ldsm4(ah1, sb + A_HI + (uint32_t)(rowa + 16) * 256 + ca);
            ldsm4(al0, sb + A_LO + (uint32_t)rowa * 256 + ca);
            ldsm4(al1, sb + A_LO + (uint32_t)(rowa + 16) * 256 + ca);
            uint32_t cb = (uint32_t)((2 * ks + subb) ^ rsb) << 4;
#pragma unroll
            for (int nb = 0; nb < NB8; nb++) {
                uint32_t rowb = (uint32_t)(wn * WN + nb * 8 + rsb);
                uint32_t bh[2], bl[2];
                ldsm2(bh, bh_base + rowb * 256 + cb);
                ldsm2(bl, bl_base + rowb * 256 + cb);
                mma16816(acc[0][nb], ah0, bh);
                mma16816(acc[1][nb], ah1, bh);
                mma16816(acc[0][nb], ah0, bl);
                mma16816(acc[1][nb], ah1, bl);
                mma16816(acc[0][nb], al0, bh);
                mma16816(acc[1][nb], al1, bh);
            }
        }

        // epilogue
#pragma unroll
        for (int mt = 0; mt < 2; mt++) {
            int row = m0 + wm * 32 + mt * 16 + (lane >> 2);
#pragma unroll
            for (int nb = 0; nb < NB8; nb++) {
                int col = wn * WN + nb * 8 + (lane & 3) * 2;
                if (FOUT == 128) {
                    __half* Yh = reinterpret_cast<__half*>(Yout);
                    __half* d0 = Yh + (size_t)t * CS + (size_t)row * 128 + col;
                    if (row < n)
                        *reinterpret_cast<__half2*>(d0) =
                            __floats2half2_rn(acc[mt][nb][0], acc[mt][nb][1]);
                    if (row + 8 < n)
                        *reinterpret_cast<__half2*>(d0 + (size_t)8 * 128) =
                            __floats2half2_rn(acc[mt][nb][2], acc[mt][nb][3]);
                } else {
                    float* Yf = reinterpret_cast<float*>(Yout);
                    float* d0 = Yf + (size_t)row * 144 + col;
                    if (row < n)
                        *reinterpret_cast<float2*>(d0) = make_float2(acc[mt][nb][0], acc[mt][nb][1]);
                    if (row + 8 < n)
                        *reinterpret_cast<float2*>(d0 + (size_t)8 * 144) =
                            make_float2(acc[mt][nb][2], acc[mt][nb][3]);
                }
            }
        }
        buf ^= 1;
    }
}

// ---------------- aggregation (flattened CSR gather over fp16 Y) ----------------
__device__ __forceinline__ void fma4(float4& a, float w, const float4 v) {
    a.x = fmaf(w, v.x, a.x); a.y = fmaf(w, v.y, a.y);
    a.z = fmaf(w, v.z, a.z); a.w = fmaf(w, v.w, a.w);
}
// load 4 consecutive fp16 Y elements (as 2 half2) and widen
__device__ __forceinline__ float4 ldY4(const __half2* Y, size_t row64, int l2) {
    uint2 u = *reinterpret_cast<const uint2*>(Y + row64 + l2);
    __half2 a = *reinterpret_cast<__half2*>(&u.x);
    __half2 b = *reinterpret_cast<__half2*>(&u.y);
    float2 fa = __half22float2(a), fb = __half22float2(b);
    return make_float4(fa.x, fa.y, fb.x, fb.y);
}
__device__ __forceinline__ size_t yrow64(int packed) {
    int src = packed & 0xFFFFF, rel = packed >> 20;
    return ((size_t)(rel + 1) * NMAX + (size_t)src) * 64;
}

// H=128 layers: one warp per node, lane covers 4 features; single flat edge loop
__global__ void agg_h_k(const float* __restrict__ bias, float* __restrict__ out,
                        int n, int relu) {
    int w = (blockIdx.x * blockDim.x + threadIdx.x) >> 5;
    int lane = threadIdx.x & 31;
    if (w >= n) return;
    const __half2* Y = reinterpret_cast<const __half2*>(g_Yh);
    const int l2 = lane * 2;
    float4 acc = ldY4(Y, (size_t)w * 64, l2);             // self term (chunk 0)
    float4 bb = *reinterpret_cast<const float4*>(bias + lane * 4);
    acc.x += bb.x; acc.y += bb.y; acc.z += bb.z; acc.w += bb.w;

    int s = g_off[w * RREL];
    const int s1 = g_off[w * RREL + RREL];
    for (; s + 4 <= s1; s += 4) {
        int p0 = g_srcs[s], p1 = g_srcs[s+1], p2 = g_srcs[s+2], p3 = g_srcs[s+3];
        float w0 = g_wt[s], w1 = g_wt[s+1], w2 = g_wt[s+2], w3 = g_wt[s+3];
        float4 v0 = ldY4(Y, yrow64(p0), l2);
        float4 v1 = ldY4(Y, yrow64(p1), l2);
        float4 v2 = ldY4(Y, yrow64(p2), l2);
        float4 v3 = ldY4(Y, yrow64(p3), l2);
        fma4(acc, w0, v0); fma4(acc, w1, v1); fma4(acc, w2, v2); fma4(acc, w3, v3);
    }
    for (; s < s1; s++) {
        float4 v = ldY4(Y, yrow64(g_srcs[s]), l2);
        fma4(acc, g_wt[s], v);
    }
    if (relu) {
        acc.x = fmaxf(acc.x, 0.f); acc.y = fmaxf(acc.y, 0.f);
        acc.z = fmaxf(acc.z, 0.f); acc.w = fmaxf(acc.w, 0.f);
    }
    *reinterpret_cast<float4*>(out + (size_t)w * 128 + lane * 4) = acc;
}

// H=16 output layer: 4 threads per node (float4 each), f32 Y row-major stride 144
__global__ void agg_o_k(const float* __restrict__ bias, float* __restrict__ out, int n) {
    int gt = blockIdx.x * blockDim.x + threadIdx.x;
    int node = gt >> 2, sub4 = (gt & 3) * 4;
    if (node >= n) return;
    const float* Y = reinterpret_cast<const float*>(g_Yh);
    float4 acc = *reinterpret_cast<const float4*>(Y + (size_t)node * 144 + sub4);
    float4 bb = *reinterpret_cast<const float4*>(bias + sub4);
    acc.x += bb.x; acc.y += bb.y; acc.z += bb.z; acc.w += bb.w;

    int s = g_off[node * RREL];
    const int s1 = g_off[node * RREL + RREL];
    for (; s + 2 <= s1; s += 2) {
        int p0 = g_srcs[s], p1 = g_srcs[s+1];
        float w0 = g_wt[s], w1 = g_wt[s+1];
        const float4 v0 = *reinterpret_cast<const float4*>(
            Y + (size_t)(p0 & 0xFFFFF) * 144 + 16 + (p0 >> 20) * 16 + sub4);
        const float4 v1 = *reinterpret_cast<const float4*>(
            Y + (size_t)(p1 & 0xFFFFF) * 144 + 16 + (p1 >> 20) * 16 + sub4);
        fma4(acc, w0, v0); fma4(acc, w1, v1);
    }
    for (; s < s1; s++) {
        int p = g_srcs[s];
        const float4 v = *reinterpret_cast<const float4*>(
            Y + (size_t)(p & 0xFFFFF) * 144 + 16 + (p >> 20) * 16 + sub4);
        fma4(acc, g_wt[s], v);
    }
    *reinterpret_cast<float4*>(out + (size_t)node * 16 + sub4) = acc;
}

// ---------------- host ----------------
extern "C" void kernel_launch(void* const* d_in, const int* in_sizes, int n_in,
                              void* d_out, int out_size) {
    const float* x  = (const float*)d_in[0];
    const int* eidx = (const int*)d_in[1];
    const int* et   = (const int*)d_in[2];
    const float* w0 = (const float*)d_in[3];
    const float* r0 = (const float*)d_in[4];
    const float* b0 = (const float*)d_in[5];
    const float* w1 = (const float*)d_in[6];
    const float* r1 = (const float*)d_in[7];
    const float* b1 = (const float*)d_in[8];
    const float* w2 = (const float*)d_in[9];
    const float* r2 = (const float*)d_in[10];
    const float* b2 = (const float*)d_in[11];
    float* out = (float*)d_out;

    int n = in_sizes[0] / FIN;   // 50000
    int e = in_sizes[2];         // 800000
    const int* src = eidx;
    const int* dst = eidx + e;

    void* Yh;
    float *h0, *h1;
    cudaGetSymbolAddress(&Yh, g_Yh);
    cudaGetSymbolAddress((void**)&h0, g_h0);
    cudaGetSymbolAddress((void**)&h1, g_h1);

    const int SMEM128 = 65536 + 2 * (2 * 128 * 256);   // A + 2 B buffers = 196608
    const int SMEM144 = 65536 + (2 * 144 * 256);       // A + 1 B buffer  = 139264
    cudaFuncSetAttribute(gemm_mma_k<128>, cudaFuncAttributeMaxDynamicSharedMemorySize, SMEM128);
    cudaFuncSetAttribute(gemm_mma_k<16>,  cudaFuncAttributeMaxDynamicSharedMemorySize, SMEM144);

    // CSR build (edge structure shared by all 3 layers)
    zero_cnt_k<<<(NB + 255) / 256, 256>>>();
    count_k<<<(e + 255) / 256, 256>>>(dst, et, e);
    scan1_k<<<SCAN_NBLK, SCAN_T>>>();
    scan2_k<<<1, SCAN_T>>>();
    scan3_k<<<(NB + 255) / 256, 256>>>(e);
    fill_k<<<(e + 255) / 256, 256>>>(src, dst, et, e);

    int mblocks = (n + 127) / 128;   // 391
    const int CB128 = (9 * 16 * 128 + 255) / 256;
    const int CB16  = (1 * 16 * 144 + 255) / 256;

    // Layer 0
    conv_b_k<128><<<CB128, 256>>>(r0, w0);
    gemm_mma_k<128><<<dim3(mblocks, 3), 256, SMEM128>>>(x, Yh, n);
    agg_h_k<<<(n * 32 + 255) / 256, 256>>>(b0, h0, n, 1);
    // Layer 1
    conv_b_k<128><<<CB128, 256>>>(r1, w1);
    gemm_mma_k<128><<<dim3(mblocks, 3), 256, SMEM128>>>(h0, Yh, n);
    agg_h_k<<<(n * 32 + 255) / 256, 256>>>(b1, h1, n, 1);
    // Layer 2 (f32 Y reusing the same buffer)
    conv_b_k<16><<<CB16, 256>>>(r2, w2);
    gemm_mma_k<16><<<dim3(mblocks, 1), 256, SMEM144>>>(h1, Yh, n);
    agg_o_k<<<(n * 4 + 255) / 256, 256>>>(b2, out, n);
}

// round 14
// speedup vs baseline: 1.8442x; 1.1160x over previous
#include <cuda_runtime.h>
#include <cuda_bf16.h>
#include <cuda_fp16.h>
#include <cstdint>

// Problem constants (fixed dataset)
#define NMAX 50000
#define NPAD 50048                  // 391 * 128
#define RREL 8
#define FIN  128
#define NB   (NMAX * RREL)          // 400000 segment bins
#define CS   ((size_t)NMAX * 128)   // Y chunk stride (elements)
#define EMAX 800000

// ---------------- device scratch (allocation-free) ----------------
__device__ __half g_Yh[9 * NMAX * 128];  // GEMM output: fp16 H-layer chunks (115MB, ~L2-resident);
                                         // reused as fp16 [node][144] for layer 2
__device__ unsigned char g_Ahi[NPAD * 256];  // pre-split, pre-swizzled A image (bf16 hi)
__device__ unsigned char g_Alo[NPAD * 256];  // (bf16 lo)
__device__ int   g_cnt[NB];
__device__ int   g_off[NB + 64];
__device__ int   g_cur[NB];
__device__ int   g_srcs[EMAX + 64];     // packed: src | (rel << 20)
__device__ float g_wt[EMAX + 64];       // per-edge 1/deg weight
__device__ float g_inv[NB];
__device__ int   g_bsum[256];
// Pre-split, pre-swizzled B images (hi/lo)
__device__ unsigned char g_Bhi[294912];
__device__ unsigned char g_Blo[294912];

// ---------------- PTX helpers (baseline sm_80-level, no 'a' features) ----------
__device__ __forceinline__ uint32_t smem_u32(const void* p) {
    uint32_t a;
    asm("{ .reg .u64 t; cvta.to.shared.u64 t, %1; cvt.u32.u64 %0, t; }" : "=r"(a) : "l"(p));
    return a;
}
__device__ __forceinline__ void ldsm4(uint32_t* r, uint32_t addr) {
    asm volatile("ldmatrix.sync.aligned.m8n8.x4.shared.b16 {%0,%1,%2,%3}, [%4];"
                 : "=r"(r[0]), "=r"(r[1]), "=r"(r[2]), "=r"(r[3]) : "r"(addr));
}
__device__ __forceinline__ void ldsm2(uint32_t* r, uint32_t addr) {
    asm volatile("ldmatrix.sync.aligned.m8n8.x2.shared.b16 {%0,%1}, [%2];"
                 : "=r"(r[0]), "=r"(r[1]) : "r"(addr));
}
__device__ __forceinline__ void mma16816(float* c, const uint32_t* a, const uint32_t* b) {
    asm volatile("mma.sync.aligned.m16n8k16.row.col.f32.bf16.bf16.f32 "
                 "{%0,%1,%2,%3}, {%4,%5,%6,%7}, {%8,%9}, {%0,%1,%2,%3};"
                 : "+f"(c[0]), "+f"(c[1]), "+f"(c[2]), "+f"(c[3])
                 : "r"(a[0]), "r"(a[1]), "r"(a[2]), "r"(a[3]), "r"(b[0]), "r"(b[1]));
}
__device__ __forceinline__ void cpa16(uint32_t smem, const void* g) {
    asm volatile("cp.async.cg.shared.global [%0], [%1], 16;" :: "r"(smem), "l"(g));
}
#define CP_COMMIT() asm volatile("cp.async.commit_group;" ::: "memory")
#define CP_WAIT0()  asm volatile("cp.async.wait_group 0;" ::: "memory")

// hi/lo bf16 split + pack pair into one u32 (low half = first element)
__device__ __forceinline__ void split_pack(float a, float b, uint32_t& hi, uint32_t& lo) {
    __nv_bfloat16 ah = __float2bfloat16(a), bh = __float2bfloat16(b);
    __nv_bfloat162 hh; hh.x = ah; hh.y = bh;
    hi = *reinterpret_cast<uint32_t*>(&hh);
    __nv_bfloat162 ll;
    ll.x = __float2bfloat16(a - __bfloat162float(ah));
    ll.y = __float2bfloat16(b - __bfloat162float(bh));
    lo = *reinterpret_cast<uint32_t*>(&ll);
}
// A-image offset for (node-row, lane): lane covers 4 f32 features = 8 bf16 bytes
__device__ __forceinline__ uint32_t aimg_off(uint32_t row, uint32_t lane) {
    return row * 256 + (((lane >> 1) ^ (row & 7)) << 4) + (lane & 1) * 8;
}

// ---------------- CSR build ----------------
__global__ void zero_cnt_k() {
    int i = blockIdx.x * blockDim.x + threadIdx.x;
    if (i < NB) g_cnt[i] = 0;
}
__global__ void count_k(const int* __restrict__ dst, const int* __restrict__ et, int e) {
    int i = blockIdx.x * blockDim.x + threadIdx.x;
    if (i < e) atomicAdd(&g_cnt[dst[i] * RREL + et[i]], 1);
}

#define SCAN_T 256
#define SCAN_I 8
#define SCAN_E (SCAN_T * SCAN_I)                 // 2048
#define SCAN_NBLK ((NB + SCAN_E - 1) / SCAN_E)   // 196

__global__ void scan1_k() {
    __shared__ int sh[SCAN_T];
    int b = blockIdx.x, t = threadIdx.x;
    int base = b * SCAN_E + t * SCAN_I;
    int v[SCAN_I]; int s = 0;
#pragma unroll
    for (int i = 0; i < SCAN_I; i++) {
        int idx = base + i;
        v[i] = (idx < NB) ? g_cnt[idx] : 0;
        s += v[i];
    }
    sh[t] = s; __syncthreads();
    for (int off = 1; off < SCAN_T; off <<= 1) {
        int x = (t >= off) ? sh[t - off] : 0;
        __syncthreads();
        sh[t] += x;
        __syncthreads();
    }
    if (t == SCAN_T - 1) g_bsum[b] = sh[t];
    int excl = sh[t] - s;
#pragma unroll
    for (int i = 0; i < SCAN_I; i++) {
        int idx = base + i;
        if (idx < NB) g_off[idx] = excl;
        excl += v[i];
    }
}
__global__ void scan2_k() {
    __shared__ int sh[SCAN_T];
    int t = threadIdx.x;
    int v = (t < SCAN_NBLK) ? g_bsum[t] : 0;
    sh[t] = v; __syncthreads();
    for (int off = 1; off < SCAN_T; off <<= 1) {
        int x = (t >= off) ? sh[t - off] : 0;
        __syncthreads();
        sh[t] += x;
        __syncthreads();
    }
    if (t < SCAN_NBLK) g_bsum[t] = sh[t] - v;
}
__global__ void scan3_k(int e) {
    int i = blockIdx.x * blockDim.x + threadIdx.x;
    if (i < NB) {
        int o = g_off[i] + g_bsum[i / SCAN_E];
        g_off[i] = o;
        g_cur[i] = o;
        int c = g_cnt[i];
        g_inv[i] = 1.0f / (float)(c > 1 ? c : 1);
    }
    if (i == 0) g_off[NB] = e;
}
__global__ void fill_k(const int* __restrict__ src, const int* __restrict__ dst,
                       const int* __restrict__ et, int e) {
    int i = blockIdx.x * blockDim.x + threadIdx.x;
    if (i < e) {
        int t = et[i];
        int bin = dst[i] * RREL + t;
        int slot = atomicAdd(&g_cur[bin], 1);
        g_srcs[slot] = src[i] | (t << 20);
        g_wt[slot] = g_inv[bin];
    }
}

// ---------------- input conversion: x -> swizzled bf16 hi/lo A image -----------
__global__ void conv_x_k(const float* __restrict__ x, int n) {
    int gt = blockIdx.x * blockDim.x + threadIdx.x;
    int node = gt >> 5, lane = gt & 31;
    if (node >= n) return;
    float4 v = *reinterpret_cast<const float4*>(x + (size_t)node * 128 + lane * 4);
    uint32_t h0, l0, h1, l1;
    split_pack(v.x, v.y, h0, l0);
    split_pack(v.z, v.w, h1, l1);
    uint32_t off = aimg_off((uint32_t)node, (uint32_t)lane);
    *reinterpret_cast<uint2*>(g_Ahi + off) = make_uint2(h0, h1);
    *reinterpret_cast<uint2*>(g_Alo + off) = make_uint2(l0, l1);
}

// ---------------- B precompute: split + swizzle weight images into global ------
template<int FOUT>
__global__ void conv_b_k(const float* __restrict__ root, const float* __restrict__ W) {
    constexpr int NT  = (FOUT == 128) ? 128 : 144;
    constexpr int TOT = (FOUT == 128) ? 9 : 1;
    int i = blockIdx.x * blockDim.x + threadIdx.x;
    if (i >= TOT * 16 * NT) return;
    int t = i / (16 * NT);
    int j = i % (16 * NT);
    int c = j / NT, ln = j % NT;
    float v[8];
#pragma unroll
    for (int kk = 0; kk < 8; kk++) {
        int k = c * 8 + kk;
        if (FOUT == 128)
            v[kk] = (t == 0) ? root[k * 128 + ln]
                             : W[((size_t)(t - 1) * 128 + k) * 128 + ln];
        else
            v[kk] = (ln < 16) ? root[k * 16 + ln]
                              : W[((size_t)((ln - 16) >> 4) * 128 + k) * 16 + ((ln - 16) & 15)];
    }
    uint32_t hi[4], lo[4];
#pragma unroll
    for (int q = 0; q < 4; q++) split_pack(v[2*q], v[2*q+1], hi[q], lo[q]);
    uint32_t off = (uint32_t)t * (NT * 256) + (uint32_t)ln * 256 + ((uint32_t)(c ^ (ln & 7)) << 4);
    *reinterpret_cast<uint4*>(g_Bhi + off) = make_uint4(hi[0], hi[1], hi[2], hi[3]);
    *reinterpret_cast<uint4*>(g_Blo + off) = make_uint4(lo[0], lo[1], lo[2], lo[3]);
}

// ---------------- HMMA GEMM: Y = A @ [root | W0..W7], hi/lo bf16 split --------
// A: cp.async from pre-split global images (g_Ahi/g_Alo). Output fp16.
// FOUT=128: 9 N-tiles of 128, Y chunked [tile][node][128]
// FOUT=16 : single N-tile of 144, Y row-major [node][144]
template<int FOUT>
__global__ void __launch_bounds__(256, 1) gemm_mma_k(void* __restrict__ Yout, int n) {
    constexpr int NT    = (FOUT == 128) ? 128 : 144;
    constexpr int TILES = (FOUT == 128) ? 3 : 1;
    constexpr int WN    = NT / 2;                     // warp N span (64 or 72)
    constexpr int NB8   = WN / 8;                     // 8 or 9
    constexpr int TB    = NT * 256;                   // tile image bytes (hi or lo)
    constexpr int A_HI = 0, A_LO = 32768, B_BASE = 65536, BSTEP = 2 * TB;

    extern __shared__ char sm[];
    const uint32_t sb = smem_u32(sm);
    const int tid = threadIdx.x, lane = tid & 31, wid = tid >> 5;
    const int wm = wid & 3, wn = wid >> 2;
    const int m0 = blockIdx.x * 128;
    const int t0 = blockIdx.y * TILES;

    // kick off A (pre-split images) + B(0) copies, all async
    {
        const unsigned char* ahi = g_Ahi + (size_t)m0 * 256;
        const unsigned char* alo = g_Alo + (size_t)m0 * 256;
        for (int i = tid; i < 2048; i += 256) {
            cpa16(sb + A_HI + i * 16, ahi + i * 16);
            cpa16(sb + A_LO + i * 16, alo + i * 16);
        }
        uint32_t b0 = sb + B_BASE;
        const unsigned char* shi = g_Bhi + (size_t)t0 * TB;
        const unsigned char* slo = g_Blo + (size_t)t0 * TB;
        for (int i = tid; i < NT * 16; i += 256) {
            cpa16(b0 + i * 16, shi + i * 16);
            cpa16(b0 + TB + i * 16, slo + i * 16);
        }
        CP_COMMIT();
    }

    // lane-invariant ldmatrix addressing
    const int sub  = lane >> 3;
    const int rowa = wm * 32 + (sub & 1) * 8 + (lane & 7);
    const int csel = sub >> 1;
    const int rs   = lane & 7;
    const int lb   = lane & 15;
    const int subb = lb >> 3;
    const int rsb  = lb & 7;

    int buf = 0;
    for (int it = 0; it < TILES; it++) {
        const int t = t0 + it;
        CP_WAIT0();
        __syncthreads();

        if (it + 1 < TILES) {
            uint32_t bn = sb + B_BASE + (buf ^ 1) * BSTEP;
            const unsigned char* shi = g_Bhi + (size_t)(t + 1) * TB;
            const unsigned char* slo = g_Blo + (size_t)(t + 1) * TB;
            for (int i = tid; i < NT * 16; i += 256) {
                cpa16(bn + i * 16, shi + i * 16);
                cpa16(bn + TB + i * 16, slo + i * 16);
            }
            CP_COMMIT();
        }

        const uint32_t bh_base = sb + B_BASE + buf * BSTEP;
        const uint32_t bl_base = bh_base + TB;

        float acc[2][NB8][4];
#pragma unroll
        for (int mt = 0; mt < 2; mt++)
#pragma unroll
            for (int nb = 0; nb < NB8; nb++)
#pragma unroll
                for (int j = 0; j < 4; j++) acc[mt][nb][j] = 0.f;

#pragma unroll
        for (int ks = 0; ks < 8; ks++) {
            uint32_t ca = (uint32_t)((2 * ks + csel) ^ rs) << 4;
            uint32_t ah0[4], ah1[4], al0[4], al1[4];
            ldsm4(ah0, sb + A_HI + (uint32_t)rowa * 256 + ca);
            ldsm4(ah1, sb + A_HI + (uint32_t)(rowa + 16) * 256 + ca);
            ldsm4(al0, sb + A_LO + (uint32_t)rowa * 256 + ca);
            ldsm4(al1, sb + A_LO + (uint32_t)(rowa + 16) * 256 + ca);
            uint32_t cb = (uint32_t)((2 * ks + subb) ^ rsb) << 4;
#pragma unroll
            for (int nb = 0; nb < NB8; nb++) {
                uint32_t rowb = (uint32_t)(wn * WN + nb * 8 + rsb);
                uint32_t bh[2], bl[2];
                ldsm2(bh, bh_base + rowb * 256 + cb);
                ldsm2(bl, bl_base + rowb * 256 + cb);
                mma16816(acc[0][nb], ah0, bh);
                mma16816(acc[1][nb], ah1, bh);
                mma16816(acc[0][nb], ah0, bl);
                mma16816(acc[1][nb], ah1, bl);
                mma16816(acc[0][nb], al0, bh);
                mma16816(acc[1][nb], al1, bh);
            }
        }

        // epilogue (fp16 output both variants)
        __half* Yh = reinterpret_cast<__half*>(Yout);
#pragma unroll
        for (int mt = 0; mt < 2; mt++) {
            int row = m0 + wm * 32 + mt * 16 + (lane >> 2);
#pragma unroll
            for (int nb = 0; nb < NB8; nb++) {
                int col = wn * WN + nb * 8 + (lane & 3) * 2;
                __half* d0;
                if (FOUT == 128) d0 = Yh + (size_t)t * CS + (size_t)row * 128 + col;
                else             d0 = Yh + (size_t)row * 144 + col;
                if (row < n)
                    *reinterpret_cast<__half2*>(d0) =
                        __floats2half2_rn(acc[mt][nb][0], acc[mt][nb][1]);
                if (row + 8 < n)
                    *reinterpret_cast<__half2*>(d0 + (size_t)8 * ((FOUT == 128) ? 128 : 144)) =
                        __floats2half2_rn(acc[mt][nb][2], acc[mt][nb][3]);
            }
        }
        buf ^= 1;
    }
}

// ---------------- aggregation (flattened CSR gather over fp16 Y) ----------------
__device__ __forceinline__ void fma4(float4& a, float w, const float4 v) {
    a.x = fmaf(w, v.x, a.x); a.y = fmaf(w, v.y, a.y);
    a.z = fmaf(w, v.z, a.z); a.w = fmaf(w, v.w, a.w);
}
// load 4 consecutive fp16 elements (8B-aligned) and widen
__device__ __forceinline__ float4 ldY4(const __half2* Y, size_t row64, int l2) {
    uint2 u = *reinterpret_cast<const uint2*>(Y + row64 + l2);
    __half2 a = *reinterpret_cast<__half2*>(&u.x);
    __half2 b = *reinterpret_cast<__half2*>(&u.y);
    float2 fa = __half22float2(a), fb = __half22float2(b);
    return make_float4(fa.x, fa.y, fb.x, fb.y);
}
__device__ __forceinline__ size_t yrow64(int packed) {
    int src = packed & 0xFFFFF, rel = packed >> 20;
    return ((size_t)(rel + 1) * NMAX + (size_t)src) * 64;
}

// H=128 layers: one warp per node; writes split A images for the next layer
__global__ void agg_h_k(const float* __restrict__ bias, int n) {
    int w = (blockIdx.x * blockDim.x + threadIdx.x) >> 5;
    int lane = threadIdx.x & 31;
    if (w >= n) return;
    const __half2* Y = reinterpret_cast<const __half2*>(g_Yh);
    const int l2 = lane * 2;
    float4 acc = ldY4(Y, (size_t)w * 64, l2);             // self term (chunk 0)
    float4 bb = *reinterpret_cast<const float4*>(bias + lane * 4);
    acc.x += bb.x; acc.y += bb.y; acc.z += bb.z; acc.w += bb.w;

    int s = g_off[w * RREL];
    const int s1 = g_off[w * RREL + RREL];
    for (; s + 4 <= s1; s += 4) {
        int p0 = g_srcs[s], p1 = g_srcs[s+1], p2 = g_srcs[s+2], p3 = g_srcs[s+3];
        float w0 = g_wt[s], w1 = g_wt[s+1], w2 = g_wt[s+2], w3 = g_wt[s+3];
        float4 v0 = ldY4(Y, yrow64(p0), l2);
        float4 v1 = ldY4(Y, yrow64(p1), l2);
        float4 v2 = ldY4(Y, yrow64(p2), l2);
        float4 v3 = ldY4(Y, yrow64(p3), l2);
        fma4(acc, w0, v0); fma4(acc, w1, v1); fma4(acc, w2, v2); fma4(acc, w3, v3);
    }
    for (; s < s1; s++) {
        float4 v = ldY4(Y, yrow64(g_srcs[s]), l2);
        fma4(acc, g_wt[s], v);
    }
    // relu + split + write swizzled A image for the next GEMM
    acc.x = fmaxf(acc.x, 0.f); acc.y = fmaxf(acc.y, 0.f);
    acc.z = fmaxf(acc.z, 0.f); acc.w = fmaxf(acc.w, 0.f);
    uint32_t h0, l0, h1, l1;
    split_pack(acc.x, acc.y, h0, l0);
    split_pack(acc.z, acc.w, h1, l1);
    uint32_t off = aimg_off((uint32_t)w, (uint32_t)lane);
    *reinterpret_cast<uint2*>(g_Ahi + off) = make_uint2(h0, h1);
    *reinterpret_cast<uint2*>(g_Alo + off) = make_uint2(l0, l1);
}

// H=16 output layer: 4 threads per node (4 fp16 each), fp16 Y row-major stride 144
__global__ void agg_o_k(const float* __restrict__ bias, float* __restrict__ out, int n) {
    int gt = blockIdx.x * blockDim.x + threadIdx.x;
    int node = gt >> 2, sub4 = (gt & 3) * 4;
    if (node >= n) return;
    const __half* Y = reinterpret_cast<const __half*>(g_Yh);
    // self term
    float4 acc;
    {
        uint2 u = *reinterpret_cast<const uint2*>(Y + (size_t)node * 144 + sub4);
        __half2 a = *reinterpret_cast<__half2*>(&u.x);
        __half2 b = *reinterpret_cast<__half2*>(&u.y);
        float2 fa = __half22float2(a), fb = __half22float2(b);
        acc = make_float4(fa.x, fa.y, fb.x, fb.y);
    }
    float4 bb = *reinterpret_cast<const float4*>(bias + sub4);
    acc.x += bb.x; acc.y += bb.y; acc.z += bb.z; acc.w += bb.w;

    int s = g_off[node * RREL];
    const int s1 = g_off[node * RREL + RREL];
    for (; s < s1; s++) {
        int p = g_srcs[s];
        float wt = g_wt[s];
        const __half* vp = Y + (size_t)(p & 0xFFFFF) * 144 + 16 + (p >> 20) * 16 + sub4;
        uint2 u = *reinterpret_cast<const uint2*>(vp);
        __half2 a = *reinterpret_cast<__half2*>(&u.x);
        __half2 b = *reinterpret_cast<__half2*>(&u.y);
        float2 fa = __half22float2(a), fb = __half22float2(b);
        fma4(acc, wt, make_float4(fa.x, fa.y, fb.x, fb.y));
    }
    *reinterpret_cast<float4*>(out + (size_t)node * 16 + sub4) = acc;
}

// ---------------- host ----------------
extern "C" void kernel_launch(void* const* d_in, const int* in_sizes, int n_in,
                              void* d_out, int out_size) {
    const float* x  = (const float*)d_in[0];
    const int* eidx = (const int*)d_in[1];
    const int* et   = (const int*)d_in[2];
    const float* w0 = (const float*)d_in[3];
    const float* r0 = (const float*)d_in[4];
    const float* b0 = (const float*)d_in[5];
    const float* w1 = (const float*)d_in[6];
    const float* r1 = (const float*)d_in[7];
    const float* b1 = (const float*)d_in[8];
    const float* w2 = (const float*)d_in[9];
    const float* r2 = (const float*)d_in[10];
    const float* b2 = (const float*)d_in[11];
    float* out = (float*)d_out;

    int n = in_sizes[0] / FIN;   // 50000
    int e = in_sizes[2];         // 800000
    const int* src = eidx;
    const int* dst = eidx + e;

    void* Yh;
    cudaGetSymbolAddress(&Yh, g_Yh);

    const int SMEM128 = 65536 + 2 * (2 * 128 * 256);   // A + 2 B buffers = 196608
    const int SMEM144 = 65536 + (2 * 144 * 256);       // A + 1 B buffer  = 139264
    cudaFuncSetAttribute(gemm_mma_k<128>, cudaFuncAttributeMaxDynamicSharedMemorySize, SMEM128);
    cudaFuncSetAttribute(gemm_mma_k<16>,  cudaFuncAttributeMaxDynamicSharedMemorySize, SMEM144);

    // CSR build (edge structure shared by all 3 layers)
    zero_cnt_k<<<(NB + 255) / 256, 256>>>();
    count_k<<<(e + 255) / 256, 256>>>(dst, et, e);
    scan1_k<<<SCAN_NBLK, SCAN_T>>>();
    scan2_k<<<1, SCAN_T>>>();
    scan3_k<<<(NB + 255) / 256, 256>>>(e);
    fill_k<<<(e + 255) / 256, 256>>>(src, dst, et, e);

    // layer-0 input -> split A images (overlaps CSR build stream-order-wise)
    conv_x_k<<<(n * 32 + 255) / 256, 256>>>(x, n);

    int mblocks = (n + 127) / 128;   // 391
    const int CB128 = (9 * 16 * 128 + 255) / 256;
    const int CB16  = (1 * 16 * 144 + 255) / 256;

    // Layer 0
    conv_b_k<128><<<CB128, 256>>>(r0, w0);
    gemm_mma_k<128><<<dim3(mblocks, 3), 256, SMEM128>>>(Yh, n);
    agg_h_k<<<(n * 32 + 255) / 256, 256>>>(b0, n);
    // Layer 1
    conv_b_k<128><<<CB128, 256>>>(r1, w1);
    gemm_mma_k<128><<<dim3(mblocks, 3), 256, SMEM128>>>(Yh, n);
    agg_h_k<<<(n * 32 + 255) / 256, 256>>>(b1, n);
    // Layer 2 (fp16 Y, stride 144)
    conv_b_k<16><<<CB16, 256>>>(r2, w2);
    gemm_mma_k<16><<<dim3(mblocks, 1), 256, SMEM144>>>(Yh, n);
    agg_o_k<<<(n * 4 + 255) / 256, 256>>>(b2, out, n);
}

// round 15
// speedup vs baseline: 2.1741x; 1.1788x over previous
#include <cuda_runtime.h>
#include <cuda_bf16.h>
#include <cuda_fp16.h>
#include <cstdint>

// Problem constants (fixed dataset)
#define NMAX 50000
#define NPAD 50048                  // 391 * 128
#define RREL 8
#define FIN  128
#define NB   (NMAX * RREL)          // 400000 segment bins
#define CS   ((size_t)NMAX * 128)   // Y chunk stride (elements)
#define EMAX 800000

// ---------------- device scratch (allocation-free) ----------------
__device__ __half g_Yh[9 * NMAX * 128];  // GEMM output: fp16 chunks (115MB, ~L2-resident);
                                         // reused as fp16 [node][144] for layer 2
__device__ unsigned char g_Ah[NPAD * 256];   // pre-swizzled fp16 A image (hi only)
__device__ int   g_cnt[NB];
__device__ int   g_off[NB + 64];
__device__ int   g_cur[NB];
__device__ int   g_srcs[EMAX + 64];     // packed: src | (rel << 20)
__device__ float g_wt[EMAX + 64];       // per-edge 1/deg weight
__device__ float g_inv[NB];
__device__ int   g_bsum[256];
// Pre-split, pre-swizzled fp16 B images (hi/lo)
__device__ unsigned char g_Bhi[294912];
__device__ unsigned char g_Blo[294912];

// ---------------- PTX helpers (baseline sm_80-level, no 'a' features) ----------
__device__ __forceinline__ uint32_t smem_u32(const void* p) {
    uint32_t a;
    asm("{ .reg .u64 t; cvta.to.shared.u64 t, %1; cvt.u32.u64 %0, t; }" : "=r"(a) : "l"(p));
    return a;
}
__device__ __forceinline__ void ldsm4(uint32_t* r, uint32_t addr) {
    asm volatile("ldmatrix.sync.aligned.m8n8.x4.shared.b16 {%0,%1,%2,%3}, [%4];"
                 : "=r"(r[0]), "=r"(r[1]), "=r"(r[2]), "=r"(r[3]) : "r"(addr));
}
__device__ __forceinline__ void ldsm2(uint32_t* r, uint32_t addr) {
    asm volatile("ldmatrix.sync.aligned.m8n8.x2.shared.b16 {%0,%1}, [%2];"
                 : "=r"(r[0]), "=r"(r[1]) : "r"(addr));
}
// fp16 HMMA, f32 accumulate (same fragment layout as the bf16 form)
__device__ __forceinline__ void mma16816h(float* c, const uint32_t* a, const uint32_t* b) {
    asm volatile("mma.sync.aligned.m16n8k16.row.col.f32.f16.f16.f32 "
                 "{%0,%1,%2,%3}, {%4,%5,%6,%7}, {%8,%9}, {%0,%1,%2,%3};"
                 : "+f"(c[0]), "+f"(c[1]), "+f"(c[2]), "+f"(c[3])
                 : "r"(a[0]), "r"(a[1]), "r"(a[2]), "r"(a[3]), "r"(b[0]), "r"(b[1]));
}
__device__ __forceinline__ void cpa16(uint32_t smem, const void* g) {
    asm volatile("cp.async.cg.shared.global [%0], [%1], 16;" :: "r"(smem), "l"(g));
}
#define CP_COMMIT() asm volatile("cp.async.commit_group;" ::: "memory")
#define CP_WAIT0()  asm volatile("cp.async.wait_group 0;" ::: "memory")

// fp16 pack pair into one u32
__device__ __forceinline__ uint32_t pack_h2(float a, float b) {
    __half2 h = __floats2half2_rn(a, b);
    return *reinterpret_cast<uint32_t*>(&h);
}
// fp16 hi/lo split + pack pair
__device__ __forceinline__ void split_pack_h(float a, float b, uint32_t& hi, uint32_t& lo) {
    __half ah = __float2half_rn(a), bh = __float2half_rn(b);
    __half2 hh; hh.x = ah; hh.y = bh;
    hi = *reinterpret_cast<uint32_t*>(&hh);
    __half2 ll;
    ll.x = __float2half_rn(a - __half2float(ah));
    ll.y = __float2half_rn(b - __half2float(bh));
    lo = *reinterpret_cast<uint32_t*>(&ll);
}
// A-image offset for (node-row, lane): lane covers 4 features = 8 bytes (4 fp16)
__device__ __forceinline__ uint32_t aimg_off(uint32_t row, uint32_t lane) {
    return row * 256 + (((lane >> 1) ^ (row & 7)) << 4) + (lane & 1) * 8;
}

// ---------------- CSR build ----------------
__global__ void zero_cnt_k() {
    int i = blockIdx.x * blockDim.x + threadIdx.x;
    if (i < NB) g_cnt[i] = 0;
}
__global__ void count_k(const int* __restrict__ dst, const int* __restrict__ et, int e) {
    int i = blockIdx.x * blockDim.x + threadIdx.x;
    if (i < e) atomicAdd(&g_cnt[dst[i] * RREL + et[i]], 1);
}

#define SCAN_T 256
#define SCAN_I 8
#define SCAN_E (SCAN_T * SCAN_I)                 // 2048
#define SCAN_NBLK ((NB + SCAN_E - 1) / SCAN_E)   // 196

__global__ void scan1_k() {
    __shared__ int sh[SCAN_T];
    int b = blockIdx.x, t = threadIdx.x;
    int base = b * SCAN_E + t * SCAN_I;
    int v[SCAN_I]; int s = 0;
#pragma unroll
    for (int i = 0; i < SCAN_I; i++) {
        int idx = base + i;
        v[i] = (idx < NB) ? g_cnt[idx] : 0;
        s += v[i];
    }
    sh[t] = s; __syncthreads();
    for (int off = 1; off < SCAN_T; off <<= 1) {
        int x = (t >= off) ? sh[t - off] : 0;
        __syncthreads();
        sh[t] += x;
        __syncthreads();
    }
    if (t == SCAN_T - 1) g_bsum[b] = sh[t];
    int excl = sh[t] - s;
#pragma unroll
    for (int i = 0; i < SCAN_I; i++) {
        int idx = base + i;
        if (idx < NB) g_off[idx] = excl;
        excl += v[i];
    }
}
__global__ void scan2_k() {
    __shared__ int sh[SCAN_T];
    int t = threadIdx.x;
    int v = (t < SCAN_NBLK) ? g_bsum[t] : 0;
    sh[t] = v; __syncthreads();
    for (int off = 1; off < SCAN_T; off <<= 1) {
        int x = (t >= off) ? sh[t - off] : 0;
        __syncthreads();
        sh[t] += x;
        __syncthreads();
    }
    if (t < SCAN_NBLK) g_bsum[t] = sh[t] - v;
}
__global__ void scan3_k(int e) {
    int i = blockIdx.x * blockDim.x + threadIdx.x;
    if (i < NB) {
        int o = g_off[i] + g_bsum[i / SCAN_E];
        g_off[i] = o;
        g_cur[i] = o;
        int c = g_cnt[i];
        g_inv[i] = 1.0f / (float)(c > 1 ? c : 1);
    }
    if (i == 0) g_off[NB] = e;
}
__global__ void fill_k(const int* __restrict__ src, const int* __restrict__ dst,
                       const int* __restrict__ et, int e) {
    int i = blockIdx.x * blockDim.x + threadIdx.x;
    if (i < e) {
        int t = et[i];
        int bin = dst[i] * RREL + t;
        int slot = atomicAdd(&g_cur[bin], 1);
        g_srcs[slot] = src[i] | (t << 20);
        g_wt[slot] = g_inv[bin];
    }
}

// ---------------- input conversion: x -> swizzled fp16 A image -----------------
__global__ void conv_x_k(const float* __restrict__ x, int n) {
    int gt = blockIdx.x * blockDim.x + threadIdx.x;
    int node = gt >> 5, lane = gt & 31;
    if (node >= n) return;
    float4 v = *reinterpret_cast<const float4*>(x + (size_t)node * 128 + lane * 4);
    uint32_t off = aimg_off((uint32_t)node, (uint32_t)lane);
    *reinterpret_cast<uint2*>(g_Ah + off) = make_uint2(pack_h2(v.x, v.y), pack_h2(v.z, v.w));
}

// ---------------- B precompute: fp16 split + swizzle weight images -------------
template<int FOUT>
__global__ void conv_b_k(const float* __restrict__ root, const float* __restrict__ W) {
    constexpr int NT  = (FOUT == 128) ? 128 : 144;
    constexpr int TOT = (FOUT == 128) ? 9 : 1;
    int i = blockIdx.x * blockDim.x + threadIdx.x;
    if (i >= TOT * 16 * NT) return;
    int t = i / (16 * NT);
    int j = i % (16 * NT);
    int c = j / NT, ln = j % NT;
    float v[8];
#pragma unroll
    for (int kk = 0; kk < 8; kk++) {
        int k = c * 8 + kk;
        if (FOUT == 128)
            v[kk] = (t == 0) ? root[k * 128 + ln]
                             : W[((size_t)(t - 1) * 128 + k) * 128 + ln];
        else
            v[kk] = (ln < 16) ? root[k * 16 + ln]
                              : W[((size_t)((ln - 16) >> 4) * 128 + k) * 16 + ((ln - 16) & 15)];
    }
    uint32_t hi[4], lo[4];
#pragma unroll
    for (int q = 0; q < 4; q++) split_pack_h(v[2*q], v[2*q+1], hi[q], lo[q]);
    uint32_t off = (uint32_t)t * (NT * 256) + (uint32_t)ln * 256 + ((uint32_t)(c ^ (ln & 7)) << 4);
    *reinterpret_cast<uint4*>(g_Bhi + off) = make_uint4(hi[0], hi[1], hi[2], hi[3]);
    *reinterpret_cast<uint4*>(g_Blo + off) = make_uint4(lo[0], lo[1], lo[2], lo[3]);
}

// ---------------- HMMA GEMM: Y = A @ [root | W0..W7], fp16 2-product ----------
// A: fp16 hi image (cp.async). B: fp16 hi/lo images. D = ah*bh + ah*bl.
// FOUT=128: 9 N-tiles of 128, Y chunked [tile][node][128]
// FOUT=16 : single N-tile of 144, Y row-major [node][144]
template<int FOUT>
__global__ void __launch_bounds__(256, 1) gemm_mma_k(void* __restrict__ Yout, int n) {
    constexpr int NT    = (FOUT == 128) ? 128 : 144;
    constexpr int TILES = (FOUT == 128) ? 3 : 1;
    constexpr int WN    = NT / 2;                     // warp N span (64 or 72)
    constexpr int NB8   = WN / 8;                     // 8 or 9
    constexpr int TB    = NT * 256;                   // tile image bytes (hi or lo)
    constexpr int A_HI = 0, B_BASE = 32768, BSTEP = 2 * TB;

    extern __shared__ char sm[];
    const uint32_t sb = smem_u32(sm);
    const int tid = threadIdx.x, lane = tid & 31, wid = tid >> 5;
    const int wm = wid & 3, wn = wid >> 2;
    const int m0 = blockIdx.x * 128;
    const int t0 = blockIdx.y * TILES;

    // kick off A + B(0) copies, all async
    {
        const unsigned char* ah = g_Ah + (size_t)m0 * 256;
        for (int i = tid; i < 2048; i += 256)
            cpa16(sb + A_HI + i * 16, ah + i * 16);
        uint32_t b0 = sb + B_BASE;
        const unsigned char* shi = g_Bhi + (size_t)t0 * TB;
        const unsigned char* slo = g_Blo + (size_t)t0 * TB;
        for (int i = tid; i < NT * 16; i += 256) {
            cpa16(b0 + i * 16, shi + i * 16);
            cpa16(b0 + TB + i * 16, slo + i * 16);
        }
        CP_COMMIT();
    }

    // lane-invariant ldmatrix addressing
    const int sub  = lane >> 3;
    const int rowa = wm * 32 + (sub & 1) * 8 + (lane & 7);
    const int csel = sub >> 1;
    const int rs   = lane & 7;
    const int lb   = lane & 15;
    const int subb = lb >> 3;
    const int rsb  = lb & 7;

    int buf = 0;
    for (int it = 0; it < TILES; it++) {
        const int t = t0 + it;
        CP_WAIT0();
        __syncthreads();

        if (it + 1 < TILES) {
            uint32_t bn = sb + B_BASE + (buf ^ 1) * BSTEP;
            const unsigned char* shi = g_Bhi + (size_t)(t + 1) * TB;
            const unsigned char* slo = g_Blo + (size_t)(t + 1) * TB;
            for (int i = tid; i < NT * 16; i += 256) {
                cpa16(bn + i * 16, shi + i * 16);
                cpa16(bn + TB + i * 16, slo + i * 16);
            }
            CP_COMMIT();
        }

        const uint32_t bh_base = sb + B_BASE + buf * BSTEP;
        const uint32_t bl_base = bh_base + TB;

        float acc[2][NB8][4];
#pragma unroll
        for (int mt = 0; mt < 2; mt++)
#pragma unroll
            for (int nb = 0; nb < NB8; nb++)
#pragma unroll
                for (int j = 0; j < 4; j++) acc[mt][nb][j] = 0.f;

#pragma unroll
        for (int ks = 0; ks < 8; ks++) {
            uint32_t ca = (uint32_t)((2 * ks + csel) ^ rs) << 4;
            uint32_t ah0[4], ah1[4];
            ldsm4(ah0, sb + A_HI + (uint32_t)rowa * 256 + ca);
            ldsm4(ah1, sb + A_HI + (uint32_t)(rowa + 16) * 256 + ca);
            uint32_t cb = (uint32_t)((2 * ks + subb) ^ rsb) << 4;
#pragma unroll
            for (int nb = 0; nb < NB8; nb++) {
                uint32_t rowb = (uint32_t)(wn * WN + nb * 8 + rsb);
                uint32_t bh[2], bl[2];
                ldsm2(bh, bh_base + rowb * 256 + cb);
                ldsm2(bl, bl_base + rowb * 256 + cb);
                mma16816h(acc[0][nb], ah0, bh);
                mma16816h(acc[1][nb], ah1, bh);
                mma16816h(acc[0][nb], ah0, bl);
                mma16816h(acc[1][nb], ah1, bl);
            }
        }

        // epilogue (fp16 output both variants)
        __half* Yh = reinterpret_cast<__half*>(Yout);
#pragma unroll
        for (int mt = 0; mt < 2; mt++) {
            int row = m0 + wm * 32 + mt * 16 + (lane >> 2);
#pragma unroll
            for (int nb = 0; nb < NB8; nb++) {
                int col = wn * WN + nb * 8 + (lane & 3) * 2;
                __half* d0;
                if (FOUT == 128) d0 = Yh + (size_t)t * CS + (size_t)row * 128 + col;
                else             d0 = Yh + (size_t)row * 144 + col;
                if (row < n)
                    *reinterpret_cast<__half2*>(d0) =
                        __floats2half2_rn(acc[mt][nb][0], acc[mt][nb][1]);
                if (row + 8 < n)
                    *reinterpret_cast<__half2*>(d0 + (size_t)8 * ((FOUT == 128) ? 128 : 144)) =
                        __floats2half2_rn(acc[mt][nb][2], acc[mt][nb][3]);
            }
        }
        buf ^= 1;
    }
}

// ---------------- aggregation (flattened CSR gather over fp16 Y) ----------------
__device__ __forceinline__ void fma4(float4& a, float w, const float4 v) {
    a.x = fmaf(w, v.x, a.x); a.y = fmaf(w, v.y, a.y);
    a.z = fmaf(w, v.z, a.z); a.w = fmaf(w, v.w, a.w);
}
// load 4 consecutive fp16 elements (8B-aligned) and widen
__device__ __forceinline__ float4 ldY4(const __half2* Y, size_t row64, int l2) {
    uint2 u = *reinterpret_cast<const uint2*>(Y + row64 + l2);
    __half2 a = *reinterpret_cast<__half2*>(&u.x);
    __half2 b = *reinterpret_cast<__half2*>(&u.y);
    float2 fa = __half22float2(a), fb = __half22float2(b);
    return make_float4(fa.x, fa.y, fb.x, fb.y);
}
__device__ __forceinline__ size_t yrow64(int packed) {
    int src = packed & 0xFFFFF, rel = packed >> 20;
    return ((size_t)(rel + 1) * NMAX + (size_t)src) * 64;
}

// H=128 layers: one warp per node; writes the fp16 A image for the next layer
__global__ void agg_h_k(const float* __restrict__ bias, int n) {
    int w = (blockIdx.x * blockDim.x + threadIdx.x) >> 5;
    int lane = threadIdx.x & 31;
    if (w >= n) return;
    const __half2* Y = reinterpret_cast<const __half2*>(g_Yh);
    const int l2 = lane * 2;
    float4 acc = ldY4(Y, (size_t)w * 64, l2);             // self term (chunk 0)
    float4 bb = *reinterpret_cast<const float4*>(bias + lane * 4);
    acc.x += bb.x; acc.y += bb.y; acc.z += bb.z; acc.w += bb.w;

    int s = g_off[w * RREL];
    const int s1 = g_off[w * RREL + RREL];
    for (; s + 4 <= s1; s += 4) {
        int p0 = g_srcs[s], p1 = g_srcs[s+1], p2 = g_srcs[s+2], p3 = g_srcs[s+3];
        float w0 = g_wt[s], w1 = g_wt[s+1], w2 = g_wt[s+2], w3 = g_wt[s+3];
        float4 v0 = ldY4(Y, yrow64(p0), l2);
        float4 v1 = ldY4(Y, yrow64(p1), l2);
        float4 v2 = ldY4(Y, yrow64(p2), l2);
        float4 v3 = ldY4(Y, yrow64(p3), l2);
        fma4(acc, w0, v0); fma4(acc, w1, v1); fma4(acc, w2, v2); fma4(acc, w3, v3);
    }
    for (; s < s1; s++) {
        float4 v = ldY4(Y, yrow64(g_srcs[s]), l2);
        fma4(acc, g_wt[s], v);
    }
    // relu + pack fp16 + write swizzled A image for the next GEMM
    acc.x = fmaxf(acc.x, 0.f); acc.y = fmaxf(acc.y, 0.f);
    acc.z = fmaxf(acc.z, 0.f); acc.w = fmaxf(acc.w, 0.f);
    uint32_t off = aimg_off((uint32_t)w, (uint32_t)lane);
    *reinterpret_cast<uint2*>(g_Ah + off) =
        make_uint2(pack_h2(acc.x, acc.y), pack_h2(acc.z, acc.w));
}

// H=16 output layer: 4 threads per node (4 fp16 each), fp16 Y row-major stride 144
__global__ void agg_o_k(const float* __restrict__ bias, float* __restrict__ out, int n) {
    int gt = blockIdx.x * blockDim.x + threadIdx.x;
    int node = gt >> 2, sub4 = (gt & 3) * 4;
    if (node >= n) return;
    const __half* Y = reinterpret_cast<const __half*>(g_Yh);
    float4 acc;
    {
        uint2 u = *reinterpret_cast<const uint2*>(Y + (size_t)node * 144 + sub4);
        __half2 a = *reinterpret_cast<__half2*>(&u.x);
        __half2 b = *reinterpret_cast<__half2*>(&u.y);
        float2 fa = __half22float2(a), fb = __half22float2(b);
        acc = make_float4(fa.x, fa.y, fb.x, fb.y);
    }
    float4 bb = *reinterpret_cast<const float4*>(bias + sub4);
    acc.x += bb.x; acc.y += bb.y; acc.z += bb.z; acc.w += bb.w;

    int s = g_off[node * RREL];
    const int s1 = g_off[node * RREL + RREL];
    for (; s < s1; s++) {
        int p = g_srcs[s];
        float wt = g_wt[s];
        const __half* vp = Y + (size_t)(p & 0xFFFFF) * 144 + 16 + (p >> 20) * 16 + sub4;
        uint2 u = *reinterpret_cast<const uint2*>(vp);
        __half2 a = *reinterpret_cast<__half2*>(&u.x);
        __half2 b = *reinterpret_cast<__half2*>(&u.y);
        float2 fa = __half22float2(a), fb = __half22float2(b);
        fma4(acc, wt, make_float4(fa.x, fa.y, fb.x, fb.y));
    }
    *reinterpret_cast<float4*>(out + (size_t)node * 16 + sub4) = acc;
}

// ---------------- host ----------------
extern "C" void kernel_launch(void* const* d_in, const int* in_sizes, int n_in,
                              void* d_out, int out_size) {
    const float* x  = (const float*)d_in[0];
    const int* eidx = (const int*)d_in[1];
    const int* et   = (const int*)d_in[2];
    const float* w0 = (const float*)d_in[3];
    const float* r0 = (const float*)d_in[4];
    const float* b0 = (const float*)d_in[5];
    const float* w1 = (const float*)d_in[6];
    const float* r1 = (const float*)d_in[7];
    const float* b1 = (const float*)d_in[8];
    const float* w2 = (const float*)d_in[9];
    const float* r2 = (const float*)d_in[10];
    const float* b2 = (const float*)d_in[11];
    float* out = (float*)d_out;

    int n = in_sizes[0] / FIN;   // 50000
    int e = in_sizes[2];         // 800000
    const int* src = eidx;
    const int* dst = eidx + e;

    void* Yh;
    cudaGetSymbolAddress(&Yh, g_Yh);

    const int SMEM128 = 32768 + 2 * (2 * 128 * 256);   // A + 2 B buffers = 163840
    const int SMEM144 = 32768 + (2 * 144 * 256);       // A + 1 B buffer  = 106496
    cudaFuncSetAttribute(gemm_mma_k<128>, cudaFuncAttributeMaxDynamicSharedMemorySize, SMEM128);
    cudaFuncSetAttribute(gemm_mma_k<16>,  cudaFuncAttributeMaxDynamicSharedMemorySize, SMEM144);

    // CSR build (edge structure shared by all 3 layers)
    zero_cnt_k<<<(NB + 255) / 256, 256>>>();
    count_k<<<(e + 255) / 256, 256>>>(dst, et, e);
    scan1_k<<<SCAN_NBLK, SCAN_T>>>();
    scan2_k<<<1, SCAN_T>>>();
    scan3_k<<<(NB + 255) / 256, 256>>>(e);
    fill_k<<<(e + 255) / 256, 256>>>(src, dst, et, e);

    // layer-0 input -> fp16 A image
    conv_x_k<<<(n * 32 + 255) / 256, 256>>>(x, n);

    int mblocks = (n + 127) / 128;   // 391
    const int CB128 = (9 * 16 * 128 + 255) / 256;
    const int CB16  = (1 * 16 * 144 + 255) / 256;

    // Layer 0
    conv_b_k<128><<<CB128, 256>>>(r0, w0);
    gemm_mma_k<128><<<dim3(mblocks, 3), 256, SMEM128>>>(Yh, n);
    agg_h_k<<<(n * 32 + 255) / 256, 256>>>(b0, n);
    // Layer 1
    conv_b_k<128><<<CB128, 256>>>(r1, w1);
    gemm_mma_k<128><<<dim3(mblocks, 3), 256, SMEM128>>>(Yh, n);
    agg_h_k<<<(n * 32 + 255) / 256, 256>>>(b1, n);
    // Layer 2 (fp16 Y, stride 144)
    conv_b_k<16><<<CB16, 256>>>(r2, w2);
    gemm_mma_k<16><<<dim3(mblocks, 1), 256, SMEM144>>>(Yh, n);
    agg_o_k<<<(n * 4 + 255) / 256, 256>>>(b2, out, n);
}

// round 16
// speedup vs baseline: 2.2504x; 1.0351x over previous
#include <cuda_runtime.h>
#include <cuda_bf16.h>
#include <cuda_fp16.h>
#include <cstdint>

// Problem constants (fixed dataset)
#define NMAX 50000
#define NPAD 50048                  // 391 * 128
#define RREL 8
#define FIN  128
#define NB   (NMAX * RREL)          // 400000 segment bins
#define CS   ((size_t)NMAX * 128)   // Y chunk stride (elements)
#define EMAX 800000

// ---------------- device scratch (allocation-free) ----------------
__device__ __half g_Yh[9 * NMAX * 128];  // GEMM output: fp16 chunks (115MB, ~L2-resident);
                                         // reused as fp16 [node][144] for layer 2
__device__ unsigned char g_Ah[NPAD * 256];   // pre-swizzled fp16 A image
__device__ int   g_cnt[NB];
__device__ int   g_off[NB + 64];
__device__ int   g_cur[NB];
__device__ int   g_srcs[EMAX + 64];     // packed: src | (rel << 20)
__device__ float g_wt[EMAX + 64];       // per-edge 1/deg weight
__device__ float g_inv[NB];
__device__ int   g_bsum[256];
// Pre-split, pre-swizzled fp16 B images (hi/lo), one set per layer
__device__ unsigned char g_B0hi[294912];
__device__ unsigned char g_B0lo[294912];
__device__ unsigned char g_B1hi[294912];
__device__ unsigned char g_B1lo[294912];
__device__ unsigned char g_B2hi[36864];
__device__ unsigned char g_B2lo[36864];

// ---------------- PTX helpers (baseline sm_80-level, no 'a' features) ----------
__device__ __forceinline__ uint32_t smem_u32(const void* p) {
    uint32_t a;
    asm("{ .reg .u64 t; cvta.to.shared.u64 t, %1; cvt.u32.u64 %0, t; }" : "=r"(a) : "l"(p));
    return a;
}
__device__ __forceinline__ void ldsm4(uint32_t* r, uint32_t addr) {
    asm volatile("ldmatrix.sync.aligned.m8n8.x4.shared.b16 {%0,%1,%2,%3}, [%4];"
                 : "=r"(r[0]), "=r"(r[1]), "=r"(r[2]), "=r"(r[3]) : "r"(addr));
}
__device__ __forceinline__ void ldsm2(uint32_t* r, uint32_t addr) {
    asm volatile("ldmatrix.sync.aligned.m8n8.x2.shared.b16 {%0,%1}, [%2];"
                 : "=r"(r[0]), "=r"(r[1]) : "r"(addr));
}
// fp16 HMMA, f32 accumulate
__device__ __forceinline__ void mma16816h(float* c, const uint32_t* a, const uint32_t* b) {
    asm volatile("mma.sync.aligned.m16n8k16.row.col.f32.f16.f16.f32 "
                 "{%0,%1,%2,%3}, {%4,%5,%6,%7}, {%8,%9}, {%0,%1,%2,%3};"
                 : "+f"(c[0]), "+f"(c[1]), "+f"(c[2]), "+f"(c[3])
                 : "r"(a[0]), "r"(a[1]), "r"(a[2]), "r"(a[3]), "r"(b[0]), "r"(b[1]));
}
__device__ __forceinline__ void cpa16(uint32_t smem, const void* g) {
    asm volatile("cp.async.cg.shared.global [%0], [%1], 16;" :: "r"(smem), "l"(g));
}
#define CP_COMMIT() asm volatile("cp.async.commit_group;" ::: "memory")
#define CP_WAIT0()  asm volatile("cp.async.wait_group 0;" ::: "memory")

// fp16 pack pair into one u32
__device__ __forceinline__ uint32_t pack_h2(float a, float b) {
    __half2 h = __floats2half2_rn(a, b);
    return *reinterpret_cast<uint32_t*>(&h);
}
// fp16 hi/lo split + pack pair
__device__ __forceinline__ void split_pack_h(float a, float b, uint32_t& hi, uint32_t& lo) {
    __half ah = __float2half_rn(a), bh = __float2half_rn(b);
    __half2 hh; hh.x = ah; hh.y = bh;
    hi = *reinterpret_cast<uint32_t*>(&hh);
    __half2 ll;
    ll.x = __float2half_rn(a - __half2float(ah));
    ll.y = __float2half_rn(b - __half2float(bh));
    lo = *reinterpret_cast<uint32_t*>(&ll);
}
// A-image offset for (node-row, lane): lane covers 4 features = 8 bytes (4 fp16)
__device__ __forceinline__ uint32_t aimg_off(uint32_t row, uint32_t lane) {
    return row * 256 + (((lane >> 1) ^ (row & 7)) << 4) + (lane & 1) * 8;
}

// ---------------- CSR build ----------------
__global__ void zero_cnt_k() {
    int i = blockIdx.x * blockDim.x + threadIdx.x;
    if (i < NB) g_cnt[i] = 0;
}
__global__ void count_k(const int* __restrict__ dst, const int* __restrict__ et, int e) {
    int i = blockIdx.x * blockDim.x + threadIdx.x;
    if (i < e) atomicAdd(&g_cnt[dst[i] * RREL + et[i]], 1);
}

#define SCAN_T 256
#define SCAN_I 8
#define SCAN_E (SCAN_T * SCAN_I)                 // 2048
#define SCAN_NBLK ((NB + SCAN_E - 1) / SCAN_E)   // 196

__global__ void scan1_k() {
    __shared__ int sh[SCAN_T];
    int b = blockIdx.x, t = threadIdx.x;
    int base = b * SCAN_E + t * SCAN_I;
    int v[SCAN_I]; int s = 0;
#pragma unroll
    for (int i = 0; i < SCAN_I; i++) {
        int idx = base + i;
        v[i] = (idx < NB) ? g_cnt[idx] : 0;
        s += v[i];
    }
    sh[t] = s; __syncthreads();
    for (int off = 1; off < SCAN_T; off <<= 1) {
        int x = (t >= off) ? sh[t - off] : 0;
        __syncthreads();
        sh[t] += x;
        __syncthreads();
    }
    if (t == SCAN_T - 1) g_bsum[b] = sh[t];
    int excl = sh[t] - s;
#pragma unroll
    for (int i = 0; i < SCAN_I; i++) {
        int idx = base + i;
        if (idx < NB) g_off[idx] = excl;
        excl += v[i];
    }
}
__global__ void scan2_k() {
    __shared__ int sh[SCAN_T];
    int t = threadIdx.x;
    int v = (t < SCAN_NBLK) ? g_bsum[t] : 0;
    sh[t] = v; __syncthreads();
    for (int off = 1; off < SCAN_T; off <<= 1) {
        int x = (t >= off) ? sh[t - off] : 0;
        __syncthreads();
        sh[t] += x;
        __syncthreads();
    }
    if (t < SCAN_NBLK) g_bsum[t] = sh[t] - v;
}
__global__ void scan3_k(int e) {
    int i = blockIdx.x * blockDim.x + threadIdx.x;
    if (i < NB) {
        int o = g_off[i] + g_bsum[i / SCAN_E];
        g_off[i] = o;
        g_cur[i] = o;
        int c = g_cnt[i];
        g_inv[i] = 1.0f / (float)(c > 1 ? c : 1);
    }
    if (i == 0) g_off[NB] = e;
}
__global__ void fill_k(const int* __restrict__ src, const int* __restrict__ dst,
                       const int* __restrict__ et, int e) {
    int i = blockIdx.x * blockDim.x + threadIdx.x;
    if (i < e) {
        int t = et[i];
        int bin = dst[i] * RREL + t;
        int slot = atomicAdd(&g_cur[bin], 1);
        g_srcs[slot] = src[i] | (t << 20);
        g_wt[slot] = g_inv[bin];
    }
}

// ---------------- input conversion: x -> swizzled fp16 A image -----------------
__global__ void conv_x_k(const float* __restrict__ x, int n) {
    int gt = blockIdx.x * blockDim.x + threadIdx.x;
    int node = gt >> 5, lane = gt & 31;
    if (node >= n) return;
    float4 v = *reinterpret_cast<const float4*>(x + (size_t)node * 128 + lane * 4);
    uint32_t off = aimg_off((uint32_t)node, (uint32_t)lane);
    *reinterpret_cast<uint2*>(g_Ah + off) = make_uint2(pack_h2(v.x, v.y), pack_h2(v.z, v.w));
}

// ---------------- B precompute: fp16 split + swizzle weight images -------------
template<int FOUT>
__global__ void conv_b_k(const float* __restrict__ root, const float* __restrict__ W,
                         unsigned char* __restrict__ Dhi, unsigned char* __restrict__ Dlo) {
    constexpr int NT  = (FOUT == 128) ? 128 : 144;
    constexpr int TOT = (FOUT == 128) ? 9 : 1;
    int i = blockIdx.x * blockDim.x + threadIdx.x;
    if (i >= TOT * 16 * NT) return;
    int t = i / (16 * NT);
    int j = i % (16 * NT);
    int c = j / NT, ln = j % NT;
    float v[8];
#pragma unroll
    for (int kk = 0; kk < 8; kk++) {
        int k = c * 8 + kk;
        if (FOUT == 128)
            v[kk] = (t == 0) ? root[k * 128 + ln]
                             : W[((size_t)(t - 1) * 128 + k) * 128 + ln];
        else
            v[kk] = (ln < 16) ? root[k * 16 + ln]
                              : W[((size_t)((ln - 16) >> 4) * 128 + k) * 16 + ((ln - 16) & 15)];
    }
    uint32_t hi[4], lo[4];
#pragma unroll
    for (int q = 0; q < 4; q++) split_pack_h(v[2*q], v[2*q+1], hi[q], lo[q]);
    uint32_t off = (uint32_t)t * (NT * 256) + (uint32_t)ln * 256 + ((uint32_t)(c ^ (ln & 7)) << 4);
    *reinterpret_cast<uint4*>(Dhi + off) = make_uint4(hi[0], hi[1], hi[2], hi[3]);
    *reinterpret_cast<uint4*>(Dlo + off) = make_uint4(lo[0], lo[1], lo[2], lo[3]);
}

// ---------------- HMMA GEMM: Y = A @ [root | W0..W7], fp16 2-product ----------
// A: fp16 image (cp.async). B: fp16 hi/lo images. D = ah*bh + ah*bl.
template<int FOUT>
__global__ void __launch_bounds__(256, 1) gemm_mma_k(const unsigned char* __restrict__ Bhi,
                                                     const unsigned char* __restrict__ Blo,
                                                     void* __restrict__ Yout, int n) {
    constexpr int NT    = (FOUT == 128) ? 128 : 144;
    constexpr int TILES = (FOUT == 128) ? 3 : 1;
    constexpr int WN    = NT / 2;                     // warp N span (64 or 72)
    constexpr int NB8   = WN / 8;                     // 8 or 9
    constexpr int TB    = NT * 256;                   // tile image bytes (hi or lo)
    constexpr int A_HI = 0, B_BASE = 32768, BSTEP = 2 * TB;

    extern __shared__ char sm[];
    const uint32_t sb = smem_u32(sm);
    const int tid = threadIdx.x, lane = tid & 31, wid = tid >> 5;
    const int wm = wid & 3, wn = wid >> 2;
    const int m0 = blockIdx.x * 128;
    const int t0 = blockIdx.y * TILES;

    // kick off A + B(0) copies, all async
    {
        const unsigned char* ah = g_Ah + (size_t)m0 * 256;
        for (int i = tid; i < 2048; i += 256)
            cpa16(sb + A_HI + i * 16, ah + i * 16);
        uint32_t b0 = sb + B_BASE;
        const unsigned char* shi = Bhi + (size_t)t0 * TB;
        const unsigned char* slo = Blo + (size_t)t0 * TB;
        for (int i = tid; i < NT * 16; i += 256) {
            cpa16(b0 + i * 16, shi + i * 16);
            cpa16(b0 + TB + i * 16, slo + i * 16);
        }
        CP_COMMIT();
    }

    // lane-invariant ldmatrix addressing
    const int sub  = lane >> 3;
    const int rowa = wm * 32 + (sub & 1) * 8 + (lane & 7);
    const int csel = sub >> 1;
    const int rs   = lane & 7;
    const int lb   = lane & 15;
    const int subb = lb >> 3;
    const int rsb  = lb & 7;

    int buf = 0;
    for (int it = 0; it < TILES; it++) {
        const int t = t0 + it;
        CP_WAIT0();
        __syncthreads();

        if (it + 1 < TILES) {
            uint32_t bn = sb + B_BASE + (buf ^ 1) * BSTEP;
            const unsigned char* shi = Bhi + (size_t)(t + 1) * TB;
            const unsigned char* slo = Blo + (size_t)(t + 1) * TB;
            for (int i = tid; i < NT * 16; i += 256) {
                cpa16(bn + i * 16, shi + i * 16);
                cpa16(bn + TB + i * 16, slo + i * 16);
            }
            CP_COMMIT();
        }

        const uint32_t bh_base = sb + B_BASE + buf * BSTEP;
        const uint32_t bl_base = bh_base + TB;

        float acc[2][NB8][4];
#pragma unroll
        for (int mt = 0; mt < 2; mt++)
#pragma unroll
            for (int nb = 0; nb < NB8; nb++)
#pragma unroll
                for (int j = 0; j < 4; j++) acc[mt][nb][j] = 0.f;

#pragma unroll
        for (int ks = 0; ks < 8; ks++) {
            uint32_t ca = (uint32_t)((2 * ks + csel) ^ rs) << 4;
            uint32_t ah0[4], ah1[4];
            ldsm4(ah0, sb + A_HI + (uint32_t)rowa * 256 + ca);
            ldsm4(ah1, sb + A_HI + (uint32_t)(rowa + 16) * 256 + ca);
            uint32_t cb = (uint32_t)((2 * ks + subb) ^ rsb) << 4;
#pragma unroll
            for (int nb = 0; nb < NB8; nb++) {
                uint32_t rowb = (uint32_t)(wn * WN + nb * 8 + rsb);
                uint32_t bh[2], bl[2];
                ldsm2(bh, bh_base + rowb * 256 + cb);
                ldsm2(bl, bl_base + rowb * 256 + cb);
                mma16816h(acc[0][nb], ah0, bh);
                mma16816h(acc[1][nb], ah1, bh);
                mma16816h(acc[0][nb], ah0, bl);
                mma16816h(acc[1][nb], ah1, bl);
            }
        }

        // epilogue (fp16 output both variants)
        __half* Yh = reinterpret_cast<__half*>(Yout);
#pragma unroll
        for (int mt = 0; mt < 2; mt++) {
            int row = m0 + wm * 32 + mt * 16 + (lane >> 2);
#pragma unroll
            for (int nb = 0; nb < NB8; nb++) {
                int col = wn * WN + nb * 8 + (lane & 3) * 2;
                __half* d0;
                if (FOUT == 128) d0 = Yh + (size_t)t * CS + (size_t)row * 128 + col;
                else             d0 = Yh + (size_t)row * 144 + col;
                if (row < n)
                    *reinterpret_cast<__half2*>(d0) =
                        __floats2half2_rn(acc[mt][nb][0], acc[mt][nb][1]);
                if (row + 8 < n)
                    *reinterpret_cast<__half2*>(d0 + (size_t)8 * ((FOUT == 128) ? 128 : 144)) =
                        __floats2half2_rn(acc[mt][nb][2], acc[mt][nb][3]);
            }
        }
        buf ^= 1;
    }
}

// ---------------- aggregation (flattened CSR gather over fp16 Y) ----------------
__device__ __forceinline__ void fma4(float4& a, float w, const float4 v) {
    a.x = fmaf(w, v.x, a.x); a.y = fmaf(w, v.y, a.y);
    a.z = fmaf(w, v.z, a.z); a.w = fmaf(w, v.w, a.w);
}
__device__ __forceinline__ float4 ldY4(const __half2* Y, size_t row64, int l2) {
    uint2 u = *reinterpret_cast<const uint2*>(Y + row64 + l2);
    __half2 a = *reinterpret_cast<__half2*>(&u.x);
    __half2 b = *reinterpret_cast<__half2*>(&u.y);
    float2 fa = __half22float2(a), fb = __half22float2(b);
    return make_float4(fa.x, fa.y, fb.x, fb.y);
}
__device__ __forceinline__ size_t yrow64(int packed) {
    int src = packed & 0xFFFFF, rel = packed >> 20;
    return ((size_t)(rel + 1) * NMAX + (size_t)src) * 64;
}

// H=128 layers: one warp per node; writes the fp16 A image for the next layer
__global__ void agg_h_k(const float* __restrict__ bias, int n) {
    int w = (blockIdx.x * blockDim.x + threadIdx.x) >> 5;
    int lane = threadIdx.x & 31;
    if (w >= n) return;
    const __half2* Y = reinterpret_cast<const __half2*>(g_Yh);
    const int l2 = lane * 2;
    float4 acc = ldY4(Y, (size_t)w * 64, l2);             // self term (chunk 0)
    float4 bb = *reinterpret_cast<const float4*>(bias + lane * 4);
    acc.x += bb.x; acc.y += bb.y; acc.z += bb.z; acc.w += bb.w;

    int s = g_off[w * RREL];
    const int s1 = g_off[w * RREL + RREL];
    for (; s + 4 <= s1; s += 4) {
        int p0 = g_srcs[s], p1 = g_srcs[s+1], p2 = g_srcs[s+2], p3 = g_srcs[s+3];
        float w0 = g_wt[s], w1 = g_wt[s+1], w2 = g_wt[s+2], w3 = g_wt[s+3];
        float4 v0 = ldY4(Y, yrow64(p0), l2);
        float4 v1 = ldY4(Y, yrow64(p1), l2);
        float4 v2 = ldY4(Y, yrow64(p2), l2);
        float4 v3 = ldY4(Y, yrow64(p3), l2);
        fma4(acc, w0, v0); fma4(acc, w1, v1); fma4(acc, w2, v2); fma4(acc, w3, v3);
    }
    for (; s < s1; s++) {
        float4 v = ldY4(Y, yrow64(g_srcs[s]), l2);
        fma4(acc, g_wt[s], v);
    }
    acc.x = fmaxf(acc.x, 0.f); acc.y = fmaxf(acc.y, 0.f);
    acc.z = fmaxf(acc.z, 0.f); acc.w = fmaxf(acc.w, 0.f);
    uint32_t off = aimg_off((uint32_t)w, (uint32_t)lane);
    *reinterpret_cast<uint2*>(g_Ah + off) =
        make_uint2(pack_h2(acc.x, acc.y), pack_h2(acc.z, acc.w));
}

// H=16 output layer: 4 threads per node (4 fp16 each), fp16 Y row-major stride 144
__global__ void agg_o_k(const float* __restrict__ bias, float* __restrict__ out, int n) {
    int gt = blockIdx.x * blockDim.x + threadIdx.x;
    int node = gt >> 2, sub4 = (gt & 3) * 4;
    if (node >= n) return;
    const __half* Y = reinterpret_cast<const __half*>(g_Yh);
    float4 acc;
    {
        uint2 u = *reinterpret_cast<const uint2*>(Y + (size_t)node * 144 + sub4);
        __half2 a = *reinterpret_cast<__half2*>(&u.x);
        __half2 b = *reinterpret_cast<__half2*>(&u.y);
        float2 fa = __half22float2(a), fb = __half22float2(b);
        acc = make_float4(fa.x, fa.y, fb.x, fb.y);
    }
    float4 bb = *reinterpret_cast<const float4*>(bias + sub4);
    acc.x += bb.x; acc.y += bb.y; acc.z += bb.z; acc.w += bb.w;

    int s = g_off[node * RREL];
    const int s1 = g_off[node * RREL + RREL];
    for (; s + 2 <= s1; s += 2) {
        int p0 = g_srcs[s], p1 = g_srcs[s+1];
        float w0 = g_wt[s], w1 = g_wt[s+1];
        const __half* vp0 = Y + (size_t)(p0 & 0xFFFFF) * 144 + 16 + (p0 >> 20) * 16 + sub4;
        const __half* vp1 = Y + (size_t)(p1 & 0xFFFFF) * 144 + 16 + (p1 >> 20) * 16 + sub4;
        uint2 u0 = *reinterpret_cast<const uint2*>(vp0);
        uint2 u1 = *reinterpret_cast<const uint2*>(vp1);
        __half2 a0 = *reinterpret_cast<__half2*>(&u0.x), b0h = *reinterpret_cast<__half2*>(&u0.y);
        __half2 a1 = *reinterpret_cast<__half2*>(&u1.x), b1h = *reinterpret_cast<__half2*>(&u1.y);
        float2 fa0 = __half22float2(a0), fb0 = __half22float2(b0h);
        float2 fa1 = __half22float2(a1), fb1 = __half22float2(b1h);
        fma4(acc, w0, make_float4(fa0.x, fa0.y, fb0.x, fb0.y));
        fma4(acc, w1, make_float4(fa1.x, fa1.y, fb1.x, fb1.y));
    }
    for (; s < s1; s++) {
        int p = g_srcs[s];
        float wt = g_wt[s];
        const __half* vp = Y + (size_t)(p & 0xFFFFF) * 144 + 16 + (p >> 20) * 16 + sub4;
        uint2 u = *reinterpret_cast<const uint2*>(vp);
        __half2 a = *reinterpret_cast<__half2*>(&u.x);
        __half2 b = *reinterpret_cast<__half2*>(&u.y);
        float2 fa = __half22float2(a), fb = __half22float2(b);
        fma4(acc, wt, make_float4(fa.x, fa.y, fb.x, fb.y));
    }
    *reinterpret_cast<float4*>(out + (size_t)node * 16 + sub4) = acc;
}

// ---------------- host ----------------
extern "C" void kernel_launch(void* const* d_in, const int* in_sizes, int n_in,
                              void* d_out, int out_size) {
    const float* x  = (const float*)d_in[0];
    const int* eidx = (const int*)d_in[1];
    const int* et   = (const int*)d_in[2];
    const float* w0 = (const float*)d_in[3];
    const float* r0 = (const float*)d_in[4];
    const float* b0 = (const float*)d_in[5];
    const float* w1 = (const float*)d_in[6];
    const float* r1 = (const float*)d_in[7];
    const float* b1 = (const float*)d_in[8];
    const float* w2 = (const float*)d_in[9];
    const float* r2 = (const float*)d_in[10];
    const float* b2 = (const float*)d_in[11];
    float* out = (float*)d_out;

    int n = in_sizes[0] / FIN;   // 50000
    int e = in_sizes[2];         // 800000
    const int* src = eidx;
    const int* dst = eidx + e;

    void* Yh;
    unsigned char *B0hi, *B0lo, *B1hi, *B1lo, *B2hi, *B2lo;
    cudaGetSymbolAddress(&Yh, g_Yh);
    cudaGetSymbolAddress((void**)&B0hi, g_B0hi);
    cudaGetSymbolAddress((void**)&B0lo, g_B0lo);
    cudaGetSymbolAddress((void**)&B1hi, g_B1hi);
    cudaGetSymbolAddress((void**)&B1lo, g_B1lo);
    cudaGetSymbolAddress((void**)&B2hi, g_B2hi);
    cudaGetSymbolAddress((void**)&B2lo, g_B2lo);

    const int SMEM128 = 32768 + 2 * (2 * 128 * 256);   // A + 2 B buffers = 163840
    const int SMEM144 = 32768 + (2 * 144 * 256);       // A + 1 B buffer  = 106496
    cudaFuncSetAttribute(gemm_mma_k<128>, cudaFuncAttributeMaxDynamicSharedMemorySize, SMEM128);
    cudaFuncSetAttribute(gemm_mma_k<16>,  cudaFuncAttributeMaxDynamicSharedMemorySize, SMEM144);

    // Fork a side stream for the CSR build (kernel_launch is only called for
    // correctness + capture, so the stream/event objects are created a handful
    // of times and intentionally not destroyed — no device memory involved).
    cudaStream_t s2;
    cudaStreamCreateWithFlags(&s2, cudaStreamNonBlocking);
    cudaEvent_t evFork, evJoin;
    cudaEventCreateWithFlags(&evFork, cudaEventDisableTiming);
    cudaEventCreateWithFlags(&evJoin, cudaEventDisableTiming);

    cudaEventRecord(evFork, 0);
    cudaStreamWaitEvent(s2, evFork, 0);

    // side stream: CSR build (needed only by agg kernels)
    zero_cnt_k<<<(NB + 255) / 256, 256, 0, s2>>>();
    count_k<<<(e + 255) / 256, 256, 0, s2>>>(dst, et, e);
    scan1_k<<<SCAN_NBLK, SCAN_T, 0, s2>>>();
    scan2_k<<<1, SCAN_T, 0, s2>>>();
    scan3_k<<<(NB + 255) / 256, 256, 0, s2>>>(e);
    fill_k<<<(e + 255) / 256, 256, 0, s2>>>(src, dst, et, e);
    cudaEventRecord(evJoin, s2);

    int mblocks = (n + 127) / 128;   // 391
    const int CB128 = (9 * 16 * 128 + 255) / 256;
    const int CB16  = (1 * 16 * 144 + 255) / 256;

    // main stream: conversions + layer-0 GEMM run concurrently with CSR build
    conv_x_k<<<(n * 32 + 255) / 256, 256>>>(x, n);
    conv_b_k<128><<<CB128, 256>>>(r0, w0, B0hi, B0lo);
    conv_b_k<128><<<CB128, 256>>>(r1, w1, B1hi, B1lo);
    conv_b_k<16><<<CB16, 256>>>(r2, w2, B2hi, B2lo);
    gemm_mma_k<128><<<dim3(mblocks, 3), 256, SMEM128>>>(B0hi, B0lo, Yh, n);

    // join: aggregation needs the CSR arrays
    cudaStreamWaitEvent(0, evJoin, 0);
    agg_h_k<<<(n * 32 + 255) / 256, 256>>>(b0, n);
    // Layer 1
    gemm_mma_k<128><<<dim3(mblocks, 3), 256, SMEM128>>>(B1hi, B1lo, Yh, n);
    agg_h_k<<<(n * 32 + 255) / 256, 256>>>(b1, n);
    // Layer 2 (fp16 Y, stride 144)
    gemm_mma_k<16><<<dim3(mblocks, 1), 256, SMEM144>>>(B2hi, B2lo, Yh, n);
    agg_o_k<<<(n * 4 + 255) / 256, 256>>>(b2, out, n);
}

// round 17
// speedup vs baseline: 2.9062x; 1.2914x over previous
#include <cuda_runtime.h>
#include <cuda_bf16.h>
#include <cuda_fp16.h>
#include <cstdint>

// Problem constants (fixed dataset)
#define NMAX 50000
#define NPAD 50048                  // 391 * 128
#define RREL 8
#define FIN  128
#define NB   (NMAX * RREL)          // 400000 segment bins
#define CS   ((size_t)NMAX * 128)   // Y chunk stride (elements)
#define EMAX 800000

// ---------------- device scratch (allocation-free) ----------------
__device__ __half g_Yh[9 * NMAX * 128];  // GEMM output: fp16 chunks (115MB, ~L2-resident);
                                         // reused as fp16 [node][144] for layer 2
__device__ unsigned char g_Ah[NPAD * 256];   // pre-swizzled fp16 A image
__device__ int   g_cnt[NB];
__device__ int   g_off[NB + 64];
__device__ int   g_cur[NB];
__device__ int   g_srcs[EMAX + 64];     // packed: src | (rel << 20)
__device__ float g_wt[EMAX + 64];       // per-edge 1/deg weight
__device__ float g_inv[NB];
__device__ int   g_bsum[256];
// Pre-swizzled fp16 B images, one per layer
__device__ unsigned char g_B0[294912];
__device__ unsigned char g_B1[294912];
__device__ unsigned char g_B2[36864];

// ---------------- PTX helpers (baseline sm_80-level, no 'a' features) ----------
__device__ __forceinline__ uint32_t smem_u32(const void* p) {
    uint32_t a;
    asm("{ .reg .u64 t; cvta.to.shared.u64 t, %1; cvt.u32.u64 %0, t; }" : "=r"(a) : "l"(p));
    return a;
}
__device__ __forceinline__ void ldsm4(uint32_t* r, uint32_t addr) {
    asm volatile("ldmatrix.sync.aligned.m8n8.x4.shared.b16 {%0,%1,%2,%3}, [%4];"
                 : "=r"(r[0]), "=r"(r[1]), "=r"(r[2]), "=r"(r[3]) : "r"(addr));
}
__device__ __forceinline__ void ldsm2(uint32_t* r, uint32_t addr) {
    asm volatile("ldmatrix.sync.aligned.m8n8.x2.shared.b16 {%0,%1}, [%2];"
                 : "=r"(r[0]), "=r"(r[1]) : "r"(addr));
}
// fp16 HMMA, f32 accumulate
__device__ __forceinline__ void mma16816h(float* c, const uint32_t* a, const uint32_t* b) {
    asm volatile("mma.sync.aligned.m16n8k16.row.col.f32.f16.f16.f32 "
                 "{%0,%1,%2,%3}, {%4,%5,%6,%7}, {%8,%9}, {%0,%1,%2,%3};"
                 : "+f"(c[0]), "+f"(c[1]), "+f"(c[2]), "+f"(c[3])
                 : "r"(a[0]), "r"(a[1]), "r"(a[2]), "r"(a[3]), "r"(b[0]), "r"(b[1]));
}
__device__ __forceinline__ void cpa16(uint32_t smem, const void* g) {
    asm volatile("cp.async.cg.shared.global [%0], [%1], 16;" :: "r"(smem), "l"(g));
}
#define CP_COMMIT() asm volatile("cp.async.commit_group;" ::: "memory")
#define CP_WAIT0()  asm volatile("cp.async.wait_group 0;" ::: "memory")

// fp16 pack pair into one u32
__device__ __forceinline__ uint32_t pack_h2(float a, float b) {
    __half2 h = __floats2half2_rn(a, b);
    return *reinterpret_cast<uint32_t*>(&h);
}
// A-image offset for (node-row, lane): lane covers 4 features = 8 bytes (4 fp16)
__device__ __forceinline__ uint32_t aimg_off(uint32_t row, uint32_t lane) {
    return row * 256 + (((lane >> 1) ^ (row & 7)) << 4) + (lane & 1) * 8;
}

// ---------------- CSR build ----------------
__global__ void zero_cnt_k() {
    int i = blockIdx.x * blockDim.x + threadIdx.x;
    if (i < NB) g_cnt[i] = 0;
}
__global__ void count_k(const int* __restrict__ dst, const int* __restrict__ et, int e) {
    int i = blockIdx.x * blockDim.x + threadIdx.x;
    if (i < e) atomicAdd(&g_cnt[dst[i] * RREL + et[i]], 1);
}

#define SCAN_T 256
#define SCAN_I 8
#define SCAN_E (SCAN_T * SCAN_I)                 // 2048
#define SCAN_NBLK ((NB + SCAN_E - 1) / SCAN_E)   // 196

__global__ void scan1_k() {
    __shared__ int sh[SCAN_T];
    int b = blockIdx.x, t = threadIdx.x;
    int base = b * SCAN_E + t * SCAN_I;
    int v[SCAN_I]; int s = 0;
#pragma unroll
    for (int i = 0; i < SCAN_I; i++) {
        int idx = base + i;
        v[i] = (idx < NB) ? g_cnt[idx] : 0;
        s += v[i];
    }
    sh[t] = s; __syncthreads();
    for (int off = 1; off < SCAN_T; off <<= 1) {
        int x = (t >= off) ? sh[t - off] : 0;
        __syncthreads();
        sh[t] += x;
        __syncthreads();
    }
    if (t == SCAN_T - 1) g_bsum[b] = sh[t];
    int excl = sh[t] - s;
#pragma unroll
    for (int i = 0; i < SCAN_I; i++) {
        int idx = base + i;
        if (idx < NB) g_off[idx] = excl;
        excl += v[i];
    }
}
__global__ void scan2_k() {
    __shared__ int sh[SCAN_T];
    int t = threadIdx.x;
    int v = (t < SCAN_NBLK) ? g_bsum[t] : 0;
    sh[t] = v; __syncthreads();
    for (int off = 1; off < SCAN_T; off <<= 1) {
        int x = (t >= off) ? sh[t - off] : 0;
        __syncthreads();
        sh[t] += x;
        __syncthreads();
    }
    if (t < SCAN_NBLK) g_bsum[t] = sh[t] - v;
}
__global__ void scan3_k(int e) {
    int i = blockIdx.x * blockDim.x + threadIdx.x;
    if (i < NB) {
        int o = g_off[i] + g_bsum[i / SCAN_E];
        g_off[i] = o;
        g_cur[i] = o;
        int c = g_cnt[i];
        g_inv[i] = 1.0f / (float)(c > 1 ? c : 1);
    }
    if (i == 0) g_off[NB] = e;
}
__global__ void fill_k(const int* __restrict__ src, const int* __restrict__ dst,
                       const int* __restrict__ et, int e) {
    int i = blockIdx.x * blockDim.x + threadIdx.x;
    if (i < e) {
        int t = et[i];
        int bin = dst[i] * RREL + t;
        int slot = atomicAdd(&g_cur[bin], 1);
        g_srcs[slot] = src[i] | (t << 20);
        g_wt[slot] = g_inv[bin];
    }
}

// ---------------- input conversion: x -> swizzled fp16 A image -----------------
__global__ void conv_x_k(const float* __restrict__ x, int n) {
    int gt = blockIdx.x * blockDim.x + threadIdx.x;
    int node = gt >> 5, lane = gt & 31;
    if (node >= n) return;
    float4 v = *reinterpret_cast<const float4*>(x + (size_t)node * 128 + lane * 4);
    uint32_t off = aimg_off((uint32_t)node, (uint32_t)lane);
    *reinterpret_cast<uint2*>(g_Ah + off) = make_uint2(pack_h2(v.x, v.y), pack_h2(v.z, v.w));
}

// ---------------- B precompute: fp16 swizzled weight images --------------------
template<int FOUT>
__global__ void conv_b_k(const float* __restrict__ root, const float* __restrict__ W,
                         unsigned char* __restrict__ Dst) {
    constexpr int NT  = (FOUT == 128) ? 128 : 144;
    constexpr int TOT = (FOUT == 128) ? 9 : 1;
    int i = blockIdx.x * blockDim.x + threadIdx.x;
    if (i >= TOT * 16 * NT) return;
    int t = i / (16 * NT);
    int j = i % (16 * NT);
    int c = j / NT, ln = j % NT;
    float v[8];
#pragma unroll
    for (int kk = 0; kk < 8; kk++) {
        int k = c * 8 + kk;
        if (FOUT == 128)
            v[kk] = (t == 0) ? root[k * 128 + ln]
                             : W[((size_t)(t - 1) * 128 + k) * 128 + ln];
        else
            v[kk] = (ln < 16) ? root[k * 16 + ln]
                              : W[((size_t)((ln - 16) >> 4) * 128 + k) * 16 + ((ln - 16) & 15)];
    }
    uint32_t h[4];
#pragma unroll
    for (int q = 0; q < 4; q++) h[q] = pack_h2(v[2*q], v[2*q+1]);
    uint32_t off = (uint32_t)t * (NT * 256) + (uint32_t)ln * 256 + ((uint32_t)(c ^ (ln & 7)) << 4);
    *reinterpret_cast<uint4*>(Dst + off) = make_uint4(h[0], h[1], h[2], h[3]);
}

// ---------------- HMMA GEMM: Y = A @ [root | W0..W7], pure fp16 ---------------
// A, B: fp16 swizzled images via cp.async. 2 CTAs/SM.
template<int FOUT>
__global__ void __launch_bounds__(256, 2) gemm_mma_k(const unsigned char* __restrict__ B,
                                                     void* __restrict__ Yout, int n) {
    constexpr int NT    = (FOUT == 128) ? 128 : 144;
    constexpr int TILES = (FOUT == 128) ? 3 : 1;
    constexpr int WN    = NT / 2;                     // warp N span (64 or 72)
    constexpr int NB8   = WN / 8;                     // 8 or 9
    constexpr int TB    = NT * 256;                   // tile image bytes
    constexpr int A_HI = 0, B_BASE = 32768;

    extern __shared__ char sm[];
    const uint32_t sb = smem_u32(sm);
    const int tid = threadIdx.x, lane = tid & 31, wid = tid >> 5;
    const int wm = wid & 3, wn = wid >> 2;
    const int m0 = blockIdx.x * 128;
    const int t0 = blockIdx.y * TILES;

    // kick off A + B(0) copies, all async
    {
        const unsigned char* ah = g_Ah + (size_t)m0 * 256;
        for (int i = tid; i < 2048; i += 256)
            cpa16(sb + A_HI + i * 16, ah + i * 16);
        const unsigned char* s0 = B + (size_t)t0 * TB;
        for (int i = tid; i < NT * 16; i += 256)
            cpa16(sb + B_BASE + i * 16, s0 + i * 16);
        CP_COMMIT();
    }

    // lane-invariant ldmatrix addressing
    const int sub  = lane >> 3;
    const int rowa = wm * 32 + (sub & 1) * 8 + (lane & 7);
    const int csel = sub >> 1;
    const int rs   = lane & 7;
    const int lb   = lane & 15;
    const int subb = lb >> 3;
    const int rsb  = lb & 7;

    int buf = 0;
    for (int it = 0; it < TILES; it++) {
        const int t = t0 + it;
        CP_WAIT0();
        __syncthreads();

        if (it + 1 < TILES) {
            uint32_t bn = sb + B_BASE + (buf ^ 1) * TB;
            const unsigned char* sn = B + (size_t)(t + 1) * TB;
            for (int i = tid; i < NT * 16; i += 256)
                cpa16(bn + i * 16, sn + i * 16);
            CP_COMMIT();
        }

        const uint32_t bh_base = sb + B_BASE + buf * TB;

        float acc[2][NB8][4];
#pragma unroll
        for (int mt = 0; mt < 2; mt++)
#pragma unroll
            for (int nb = 0; nb < NB8; nb++)
#pragma unroll
                for (int j = 0; j < 4; j++) acc[mt][nb][j] = 0.f;

#pragma unroll
        for (int ks = 0; ks < 8; ks++) {
            uint32_t ca = (uint32_t)((2 * ks + csel) ^ rs) << 4;
            uint32_t ah0[4], ah1[4];
            ldsm4(ah0, sb + A_HI + (uint32_t)rowa * 256 + ca);
            ldsm4(ah1, sb + A_HI + (uint32_t)(rowa + 16) * 256 + ca);
            uint32_t cb = (uint32_t)((2 * ks + subb) ^ rsb) << 4;
#pragma unroll
            for (int nb = 0; nb < NB8; nb++) {
                uint32_t rowb = (uint32_t)(wn * WN + nb * 8 + rsb);
                uint32_t bh[2];
                ldsm2(bh, bh_base + rowb * 256 + cb);
                mma16816h(acc[0][nb], ah0, bh);
                mma16816h(acc[1][nb], ah1, bh);
            }
        }

        // epilogue (fp16 output both variants)
        __half* Yh = reinterpret_cast<__half*>(Yout);
#pragma unroll
        for (int mt = 0; mt < 2; mt++) {
            int row = m0 + wm * 32 + mt * 16 + (lane >> 2);
#pragma unroll
            for (int nb = 0; nb < NB8; nb++) {
                int col = wn * WN + nb * 8 + (lane & 3) * 2;
                __half* d0;
                if (FOUT == 128) d0 = Yh + (size_t)t * CS + (size_t)row * 128 + col;
                else             d0 = Yh + (size_t)row * 144 + col;
                if (row < n)
                    *reinterpret_cast<__half2*>(d0) =
                        __floats2half2_rn(acc[mt][nb][0], acc[mt][nb][1]);
                if (row + 8 < n)
                    *reinterpret_cast<__half2*>(d0 + (size_t)8 * ((FOUT == 128) ? 128 : 144)) =
                        __floats2half2_rn(acc[mt][nb][2], acc[mt][nb][3]);
            }
        }
        buf ^= 1;
    }
}

// ---------------- aggregation (flattened CSR gather over fp16 Y) ----------------
__device__ __forceinline__ void fma4(float4& a, float w, const float4 v) {
    a.x = fmaf(w, v.x, a.x); a.y = fmaf(w, v.y, a.y);
    a.z = fmaf(w, v.z, a.z); a.w = fmaf(w, v.w, a.w);
}
__device__ __forceinline__ float4 ldY4(const __half2* Y, size_t row64, int l2) {
    uint2 u = *reinterpret_cast<const uint2*>(Y + row64 + l2);
    __half2 a = *reinterpret_cast<__half2*>(&u.x);
    __half2 b = *reinterpret_cast<__half2*>(&u.y);
    float2 fa = __half22float2(a), fb = __half22float2(b);
    return make_float4(fa.x, fa.y, fb.x, fb.y);
}
__device__ __forceinline__ size_t yrow64(int packed) {
    int src = packed & 0xFFFFF, rel = packed >> 20;
    return ((size_t)(rel + 1) * NMAX + (size_t)src) * 64;
}

// H=128 layers: one warp per node; writes the fp16 A image for the next layer
__global__ void agg_h_k(const float* __restrict__ bias, int n) {
    int w = (blockIdx.x * blockDim.x + threadIdx.x) >> 5;
    int lane = threadIdx.x & 31;
    if (w >= n) return;
    const __half2* Y = reinterpret_cast<const __half2*>(g_Yh);
    const int l2 = lane * 2;
    float4 acc = ldY4(Y, (size_t)w * 64, l2);             // self term (chunk 0)
    float4 bb = *reinterpret_cast<const float4*>(bias + lane * 4);
    acc.x += bb.x; acc.y += bb.y; acc.z += bb.z; acc.w += bb.w;

    int s = g_off[w * RREL];
    const int s1 = g_off[w * RREL + RREL];
    for (; s + 4 <= s1; s += 4) {
        int p0 = g_srcs[s], p1 = g_srcs[s+1], p2 = g_srcs[s+2], p3 = g_srcs[s+3];
        float w0 = g_wt[s], w1 = g_wt[s+1], w2 = g_wt[s+2], w3 = g_wt[s+3];
        float4 v0 = ldY4(Y, yrow64(p0), l2);
        float4 v1 = ldY4(Y, yrow64(p1), l2);
        float4 v2 = ldY4(Y, yrow64(p2), l2);
        float4 v3 = ldY4(Y, yrow64(p3), l2);
        fma4(acc, w0, v0); fma4(acc, w1, v1); fma4(acc, w2, v2); fma4(acc, w3, v3);
    }
    for (; s < s1; s++) {
        float4 v = ldY4(Y, yrow64(g_srcs[s]), l2);
        fma4(acc, g_wt[s], v);
    }
    acc.x = fmaxf(acc.x, 0.f); acc.y = fmaxf(acc.y, 0.f);
    acc.z = fmaxf(acc.z, 0.f); acc.w = fmaxf(acc.w, 0.f);
    uint32_t off = aimg_off((uint32_t)w, (uint32_t)lane);
    *reinterpret_cast<uint2*>(g_Ah + off) =
        make_uint2(pack_h2(acc.x, acc.y), pack_h2(acc.z, acc.w));
}

// H=16 output layer: 4 threads per node (4 fp16 each), fp16 Y row-major stride 144
__global__ void agg_o_k(const float* __restrict__ bias, float* __restrict__ out, int n) {
    int gt = blockIdx.x * blockDim.x + threadIdx.x;
    int node = gt >> 2, sub4 = (gt & 3) * 4;
    if (node >= n) return;
    const __half* Y = reinterpret_cast<const __half*>(g_Yh);
    float4 acc;
    {
        uint2 u = *reinterpret_cast<const uint2*>(Y + (size_t)node * 144 + sub4);
        __half2 a = *reinterpret_cast<__half2*>(&u.x);
        __half2 b = *reinterpret_cast<__half2*>(&u.y);
        float2 fa = __half22float2(a), fb = __half22float2(b);
        acc = make_float4(fa.x, fa.y, fb.x, fb.y);
    }
    float4 bb = *reinterpret_cast<const float4*>(bias + sub4);
    acc.x += bb.x; acc.y += bb.y; acc.z += bb.z; acc.w += bb.w;

    int s = g_off[node * RREL];
    const int s1 = g_off[node * RREL + RREL];
    for (; s + 2 <= s1; s += 2) {
        int p0 = g_srcs[s], p1 = g_srcs[s+1];
        float w0 = g_wt[s], w1 = g_wt[s+1];
        const __half* vp0 = Y + (size_t)(p0 & 0xFFFFF) * 144 + 16 + (p0 >> 20) * 16 + sub4;
        const __half* vp1 = Y + (size_t)(p1 & 0xFFFFF) * 144 + 16 + (p1 >> 20) * 16 + sub4;
        uint2 u0 = *reinterpret_cast<const uint2*>(vp0);
        uint2 u1 = *reinterpret_cast<const uint2*>(vp1);
        __half2 a0 = *reinterpret_cast<__half2*>(&u0.x), b0h = *reinterpret_cast<__half2*>(&u0.y);
        __half2 a1 = *reinterpret_cast<__half2*>(&u1.x), b1h = *reinterpret_cast<__half2*>(&u1.y);
        float2 fa0 = __half22float2(a0), fb0 = __half22float2(b0h);
        float2 fa1 = __half22float2(a1), fb1 = __half22float2(b1h);
        fma4(acc, w0, make_float4(fa0.x, fa0.y, fb0.x, fb0.y));
        fma4(acc, w1, make_float4(fa1.x, fa1.y, fb1.x, fb1.y));
    }
    for (; s < s1; s++) {
        int p = g_srcs[s];
        float wt = g_wt[s];
        const __half* vp = Y + (size_t)(p & 0xFFFFF) * 144 + 16 + (p >> 20) * 16 + sub4;
        uint2 u = *reinterpret_cast<const uint2*>(vp);
        __half2 a = *reinterpret_cast<__half2*>(&u.x);
        __half2 b = *reinterpret_cast<__half2*>(&u.y);
        float2 fa = __half22float2(a), fb = __half22float2(b);
        fma4(acc, wt, make_float4(fa.x, fa.y, fb.x, fb.y));
    }
    *reinterpret_cast<float4*>(out + (size_t)node * 16 + sub4) = acc;
}

// ---------------- host ----------------
extern "C" void kernel_launch(void* const* d_in, const int* in_sizes, int n_in,
                              void* d_out, int out_size) {
    const float* x  = (const float*)d_in[0];
    const int* eidx = (const int*)d_in[1];
    const int* et   = (const int*)d_in[2];
    const float* w0 = (const float*)d_in[3];
    const float* r0 = (const float*)d_in[4];
    const float* b0 = (const float*)d_in[5];
    const float* w1 = (const float*)d_in[6];
    const float* r1 = (const float*)d_in[7];
    const float* b1 = (const float*)d_in[8];
    const float* w2 = (const float*)d_in[9];
    const float* r2 = (const float*)d_in[10];
    const float* b2 = (const float*)d_in[11];
    float* out = (float*)d_out;

    int n = in_sizes[0] / FIN;   // 50000
    int e = in_sizes[2];         // 800000
    const int* src = eidx;
    const int* dst = eidx + e;

    void* Yh;
    unsigned char *B0, *B1, *B2;
    cudaGetSymbolAddress(&Yh, g_Yh);
    cudaGetSymbolAddress((void**)&B0, g_B0);
    cudaGetSymbolAddress((void**)&B1, g_B1);
    cudaGetSymbolAddress((void**)&B2, g_B2);

    const int SMEM128 = 32768 + 2 * (128 * 256);   // A + 2 B buffers = 98304 -> 2 CTAs/SM
    const int SMEM144 = 32768 + (144 * 256);       // A + 1 B buffer  = 69632
    cudaFuncSetAttribute(gemm_mma_k<128>, cudaFuncAttributeMaxDynamicSharedMemorySize, SMEM128);
    cudaFuncSetAttribute(gemm_mma_k<16>,  cudaFuncAttributeMaxDynamicSharedMemorySize, SMEM144);

    // Fork a side stream for the CSR build (stream/event objects are created
    // only on the few non-replay calls; no device memory involved).
    cudaStream_t s2;
    cudaStreamCreateWithFlags(&s2, cudaStreamNonBlocking);
    cudaEvent_t evFork, evJoin;
    cudaEventCreateWithFlags(&evFork, cudaEventDisableTiming);
    cudaEventCreateWithFlags(&evJoin, cudaEventDisableTiming);

    cudaEventRecord(evFork, 0);
    cudaStreamWaitEvent(s2, evFork, 0);

    // side stream: CSR build (needed only by agg kernels)
    zero_cnt_k<<<(NB + 255) / 256, 256, 0, s2>>>();
    count_k<<<(e + 255) / 256, 256, 0, s2>>>(dst, et, e);
    scan1_k<<<SCAN_NBLK, SCAN_T, 0, s2>>>();
    scan2_k<<<1, SCAN_T, 0, s2>>>();
    scan3_k<<<(NB + 255) / 256, 256, 0, s2>>>(e);
    fill_k<<<(e + 255) / 256, 256, 0, s2>>>(src, dst, et, e);
    cudaEventRecord(evJoin, s2);

    int mblocks = (n + 127) / 128;   // 391
    const int CB128 = (9 * 16 * 128 + 255) / 256;
    const int CB16  = (1 * 16 * 144 + 255) / 256;

    // main stream: conversions + layer-0 GEMM run concurrently with CSR build
    conv_x_k<<<(n * 32 + 255) / 256, 256>>>(x, n);
    conv_b_k<128><<<CB128, 256>>>(r0, w0, B0);
    conv_b_k<128><<<CB128, 256>>>(r1, w1, B1);
    conv_b_k<16><<<CB16, 256>>>(r2, w2, B2);
    gemm_mma_k<128><<<dim3(mblocks, 3), 256, SMEM128>>>(B0, Yh, n);

    // join: aggregation needs the CSR arrays
    cudaStreamWaitEvent(0, evJoin, 0);
    agg_h_k<<<(n * 32 + 255) / 256, 256>>>(b0, n);
    // Layer 1
    gemm_mma_k<128><<<dim3(mblocks, 3), 256, SMEM128>>>(B1, Yh, n);
    agg_h_k<<<(n * 32 + 255) / 256, 256>>>(b1, n);
    // Layer 2 (fp16 Y, stride 144)
    gemm_mma_k<16><<<dim3(mblocks, 1), 256, SMEM144>>>(B2, Yh, n);
    agg_o_k<<<(n * 4 + 255) / 256, 256>>>(b2, out, n);
}